// round 8
// baseline (speedup 1.0000x reference)
#include <cuda_runtime.h>
#include <math.h>

// ---------------- static scratch (no runtime allocation allowed) ------------
#define NMAX 100000
#define EMAX 1600000
#define ENMAX (EMAX + NMAX)

__device__ float g_h[(size_t)NMAX * 128];     // h1 (layer1 GEMM out), reused as h2
__device__ float g_feat[(size_t)NMAX * 128];  // layer1 output features
__device__ float g_ss[NMAX];                  // per-node src score
__device__ float g_sd[NMAX];                  // per-node dst score
__device__ int   g_deg[NMAX];
__device__ int   g_rowptr[NMAX + 1];
__device__ int   g_cursor[NMAX];
__device__ int   g_srcidx[ENMAX];
__device__ int   g_is64;                      // edge_index dtype flag

// ---------------- dtype probe ----------------------------------------------
// int64 indices < 2^31 have zero high words at all odd int32 positions.
__global__ void k_probe(const int* __restrict__ ei32) {
    if (threadIdx.x == 0 && blockIdx.x == 0) {
        int acc = ei32[1] | ei32[3] | ei32[5] | ei32[7] |
                  ei32[9] | ei32[11] | ei32[13] | ei32[15];
        g_is64 = (acc == 0) ? 1 : 0;
    }
}

__device__ __forceinline__ int load_src(const int* ei32, int E, int i) {
    int v = g_is64 ? ei32[2 * i] : ei32[i];
    return min(max(v, 0), NMAX - 1);
}
__device__ __forceinline__ int load_dst(const int* ei32, int E, int i) {
    int v = g_is64 ? ei32[2 * (E + i)] : ei32[E + i];
    return min(max(v, 0), NMAX - 1);
}

// ---------------- CSR build -------------------------------------------------
__global__ void k_initdeg(int N) {
    int i = blockIdx.x * blockDim.x + threadIdx.x;
    if (i < N) g_deg[i] = 1;  // self loop
}

__global__ void k_count(const int* __restrict__ ei32, int E) {
    int i = blockIdx.x * blockDim.x + threadIdx.x;
    if (i < E) atomicAdd(&g_deg[load_dst(ei32, E, i)], 1);
}

__global__ __launch_bounds__(1024) void k_scan(int n) {
    __shared__ int part[1024];
    int tid = threadIdx.x;
    int chunk = (n + 1023) >> 10;
    int start = tid * chunk;
    int end = min(start + chunk, n);
    int s = 0;
    for (int i = start; i < end; i++) s += g_deg[i];
    part[tid] = s;
    __syncthreads();
    for (int off = 1; off < 1024; off <<= 1) {
        int v = (tid >= off) ? part[tid - off] : 0;
        __syncthreads();
        part[tid] += v;
        __syncthreads();
    }
    int run = (tid == 0) ? 0 : part[tid - 1];
    for (int i = start; i < end; i++) {
        g_rowptr[i] = run;
        g_cursor[i] = run;
        run += g_deg[i];
    }
    if (tid == 1023) g_rowptr[n] = part[1023];
}

__global__ void k_fill(const int* __restrict__ ei32, int E, int N) {
    int i = blockIdx.x * blockDim.x + threadIdx.x;
    if (i >= E + N) return;
    int s, d;
    if (i < E) {
        s = load_src(ei32, E, i);
        d = load_dst(ei32, E, i);
    } else {
        s = d = i - E;
    }
    int pos = atomicAdd(&g_cursor[d], 1);
    if (pos >= 0 && pos < ENMAX) g_srcidx[pos] = s;
}

// ---------------- SGEMM: C[M,N] = A[M,K] @ B[K,N], row major ---------------
// a_sel: 0 = external A pointer, 1 = g_feat ; c_sel: 0 = g_h, 1 = g_feat
#define BM 128
#define BN 128
#define BKK 8
#define TM 8
#define TN 8

__global__ __launch_bounds__(256) void k_sgemm(int M, int N, int K,
                                               const float* __restrict__ Aext,
                                               const float* __restrict__ B,
                                               int a_sel, int c_sel) {
    const float* A = (a_sel == 0) ? Aext : (const float*)g_feat;
    float* C = (c_sel == 0) ? g_h : g_feat;

    __shared__ __align__(16) float As[BKK][BM];
    __shared__ __align__(16) float Bs[BKK][BN];
    int tid = threadIdx.x;
    int rowBase = blockIdx.y * BM;
    int colBase = blockIdx.x * BN;
    int aRow = tid >> 1;
    int aCol = (tid & 1) << 2;
    int bRow = tid >> 5;
    int bCol = (tid & 31) << 2;
    int tr = (tid >> 4) * TM;
    int tc = (tid & 15) * TN;
    float acc[TM][TN];
#pragma unroll
    for (int i = 0; i < TM; i++)
#pragma unroll
        for (int j = 0; j < TN; j++) acc[i][j] = 0.f;

    for (int k0 = 0; k0 < K; k0 += BKK) {
        float4 av = make_float4(0.f, 0.f, 0.f, 0.f);
        int gr = rowBase + aRow;
        if (gr < M)
            av = *reinterpret_cast<const float4*>(&A[(size_t)gr * K + k0 + aCol]);
        As[aCol + 0][aRow] = av.x;
        As[aCol + 1][aRow] = av.y;
        As[aCol + 2][aRow] = av.z;
        As[aCol + 3][aRow] = av.w;

        float4 bv = make_float4(0.f, 0.f, 0.f, 0.f);
        int gc = colBase + bCol;
        const float* brow = &B[(size_t)(k0 + bRow) * N];
        if (gc + 3 < N) {
            bv = *reinterpret_cast<const float4*>(&brow[gc]);
        } else if (gc < N) {
            bv.x = brow[gc];
            if (gc + 1 < N) bv.y = brow[gc + 1];
            if (gc + 2 < N) bv.z = brow[gc + 2];
        }
        *reinterpret_cast<float4*>(&Bs[bRow][bCol]) = bv;
        __syncthreads();
#pragma unroll
        for (int k = 0; k < BKK; k++) {
            float ra[TM], rb[TN];
#pragma unroll
            for (int i = 0; i < TM; i++) ra[i] = As[k][tr + i];
#pragma unroll
            for (int j = 0; j < TN; j++) rb[j] = Bs[k][tc + j];
#pragma unroll
            for (int i = 0; i < TM; i++)
#pragma unroll
                for (int j = 0; j < TN; j++) acc[i][j] += ra[i] * rb[j];
        }
        __syncthreads();
    }
#pragma unroll
    for (int i = 0; i < TM; i++) {
        int r = rowBase + tr + i;
        if (r >= M) continue;
        float* crow = &C[(size_t)r * N];
#pragma unroll
        for (int j = 0; j < TN; j += 4) {
            int c = colBase + tc + j;
            if (c + 3 < N) {
                float4 v = make_float4(acc[i][j], acc[i][j + 1], acc[i][j + 2], acc[i][j + 3]);
                *reinterpret_cast<float4*>(&crow[c]) = v;
            } else {
#pragma unroll
                for (int jj = 0; jj < 4; jj++)
                    if (c + jj < N) crow[c + jj] = acc[i][j + jj];
            }
        }
    }
}

// ---------------- per-node attention scores: s = h . a ----------------------
__global__ __launch_bounds__(256) void k_score(const float* __restrict__ asrc,
                                               const float* __restrict__ adst,
                                               int N, int W) {
    int warp = (blockIdx.x * blockDim.x + threadIdx.x) >> 5;
    int lane = threadIdx.x & 31;
    if (warp >= N) return;
    const float* row = g_h + (size_t)warp * W;
    float s = 0.f, d = 0.f;
    for (int c = lane; c < W; c += 32) {
        float v = row[c];
        s += v * asrc[c];
        d += v * adst[c];
    }
#pragma unroll
    for (int o = 16; o; o >>= 1) {
        s += __shfl_xor_sync(0xffffffffu, s, o);
        d += __shfl_xor_sync(0xffffffffu, d, o);
    }
    if (lane == 0) {
        g_ss[warp] = s;
        g_sd[warp] = d;
    }
}

// ---------------- layer1 aggregation (H=128), fused bias+ReLU ---------------
// software-pipelined gather: next srcidx + next h row prefetched each iter
__global__ __launch_bounds__(256) void k_agg1(const float* __restrict__ bias, int N) {
    int warp = (blockIdx.x * blockDim.x + threadIdx.x) >> 5;
    int lane = threadIdx.x & 31;
    if (warp >= N) return;
    int rp = g_rowptr[warp], re = g_rowptr[warp + 1];
    float sd = g_sd[warp];
    float mx = -3.402823466e38f;
    for (int j = rp + lane; j < re; j += 32) {
        float e = g_ss[g_srcidx[j]] + sd;
        e = e > 0.f ? e : 0.2f * e;
        mx = fmaxf(mx, e);
    }
#pragma unroll
    for (int o = 16; o; o >>= 1) mx = fmaxf(mx, __shfl_xor_sync(0xffffffffu, mx, o));

    float4 acc = make_float4(0.f, 0.f, 0.f, 0.f);
    float denom = 0.f;
    int coff = lane << 2;
    // pipeline: stage j's loads issued before consuming stage j-1
    int s_cur = (rp < re) ? g_srcidx[rp] : 0;
    float ss_cur = (rp < re) ? g_ss[s_cur] : 0.f;
    float4 hv_cur = (rp < re)
        ? *reinterpret_cast<const float4*>(&g_h[(size_t)s_cur * 128 + coff])
        : make_float4(0.f, 0.f, 0.f, 0.f);
    for (int j = rp; j < re; j++) {
        int s_nxt = 0; float ss_nxt = 0.f;
        float4 hv_nxt = make_float4(0.f, 0.f, 0.f, 0.f);
        if (j + 1 < re) {
            s_nxt = g_srcidx[j + 1];
            ss_nxt = g_ss[s_nxt];
            hv_nxt = *reinterpret_cast<const float4*>(&g_h[(size_t)s_nxt * 128 + coff]);
        }
        float e = ss_cur + sd;
        e = e > 0.f ? e : 0.2f * e;
        float ex = __expf(e - mx);
        denom += ex;
        acc.x += ex * hv_cur.x;
        acc.y += ex * hv_cur.y;
        acc.z += ex * hv_cur.z;
        acc.w += ex * hv_cur.w;
        ss_cur = ss_nxt;
        hv_cur = hv_nxt;
    }
    float inv = 1.f / denom;
    float4 o;
    o.x = fmaxf(fmaf(acc.x, inv, bias[coff + 0]), 0.f);
    o.y = fmaxf(fmaf(acc.y, inv, bias[coff + 1]), 0.f);
    o.z = fmaxf(fmaf(acc.z, inv, bias[coff + 2]), 0.f);
    o.w = fmaxf(fmaf(acc.w, inv, bias[coff + 3]), 0.f);
    *reinterpret_cast<float4*>(&g_feat[(size_t)warp * 128 + coff]) = o;
}

// ---------------- layer2 aggregation (C<=64) + fused log_softmax ------------
__global__ __launch_bounds__(256) void k_agg2(const float* __restrict__ bias,
                                              float* __restrict__ out, int N, int C) {
    int warp = (blockIdx.x * blockDim.x + threadIdx.x) >> 5;
    int lane = threadIdx.x & 31;
    if (warp >= N) return;
    int rp = g_rowptr[warp], re = g_rowptr[warp + 1];
    float sd = g_sd[warp];
    float mx = -3.402823466e38f;
    for (int j = rp + lane; j < re; j += 32) {
        float e = g_ss[g_srcidx[j]] + sd;
        e = e > 0.f ? e : 0.2f * e;
        mx = fmaxf(mx, e);
    }
#pragma unroll
    for (int o = 16; o; o >>= 1) mx = fmaxf(mx, __shfl_xor_sync(0xffffffffu, mx, o));

    int c0 = lane, c1 = lane + 32;
    bool v0ok = c0 < C, v1ok = c1 < C;
    float a0 = 0.f, a1 = 0.f, denom = 0.f;
    int s_cur = (rp < re) ? g_srcidx[rp] : 0;
    float ss_cur = (rp < re) ? g_ss[s_cur] : 0.f;
    float h0_cur = 0.f, h1_cur = 0.f;
    if (rp < re) {
        const float* hr = &g_h[(size_t)s_cur * C];
        if (v0ok) h0_cur = hr[c0];
        if (v1ok) h1_cur = hr[c1];
    }
    for (int j = rp; j < re; j++) {
        float ss_nxt = 0.f, h0_nxt = 0.f, h1_nxt = 0.f;
        if (j + 1 < re) {
            int s_nxt = g_srcidx[j + 1];
            ss_nxt = g_ss[s_nxt];
            const float* hr = &g_h[(size_t)s_nxt * C];
            if (v0ok) h0_nxt = hr[c0];
            if (v1ok) h1_nxt = hr[c1];
        }
        float e = ss_cur + sd;
        e = e > 0.f ? e : 0.2f * e;
        float ex = __expf(e - mx);
        denom += ex;
        a0 += ex * h0_cur;
        a1 += ex * h1_cur;
        ss_cur = ss_nxt;
        h0_cur = h0_nxt;
        h1_cur = h1_nxt;
    }
    float inv = 1.f / denom;
    float v0 = v0ok ? fmaf(a0, inv, bias[c0]) : -3.402823466e38f;
    float v1 = v1ok ? fmaf(a1, inv, bias[c1]) : -3.402823466e38f;
    float m2 = fmaxf(v0, v1);
#pragma unroll
    for (int o = 16; o; o >>= 1) m2 = fmaxf(m2, __shfl_xor_sync(0xffffffffu, m2, o));
    float se = (v0ok ? __expf(v0 - m2) : 0.f) + (v1ok ? __expf(v1 - m2) : 0.f);
#pragma unroll
    for (int o = 16; o; o >>= 1) se += __shfl_xor_sync(0xffffffffu, se, o);
    float lse = m2 + logf(se);
    if (v0ok) out[(size_t)warp * C + c0] = v0 - lse;
    if (v1ok) out[(size_t)warp * C + c1] = v1 - lse;
}

// ---------------- launcher --------------------------------------------------
static inline int cdiv(int a, int b) { return (a + b - 1) / b; }

extern "C" void kernel_launch(void* const* d_in, const int* in_sizes, int n_in,
                              void* d_out, int out_size) {
    const float* x   = (const float*)d_in[0];
    const int* ei32  = (const int*)d_in[1];   // edge_index (int32, or int64 detected on device)
    const float* W1  = (const float*)d_in[2];
    const float* as1 = (const float*)d_in[3];
    const float* ad1 = (const float*)d_in[4];
    const float* b1  = (const float*)d_in[5];
    const float* W2  = (const float*)d_in[6];
    const float* as2 = (const float*)d_in[7];
    const float* ad2 = (const float*)d_in[8];
    const float* b2  = (const float*)d_in[9];

    int H = in_sizes[3];
    int C = in_sizes[7];
    int F = in_sizes[2] / H;
    int N = in_sizes[0] / F;
    int E = in_sizes[1] / 2;   // element count / 2, dtype-invariant

    // dtype probe + CSR build (shared by both layers)
    k_probe<<<1, 32>>>(ei32);
    k_initdeg<<<cdiv(N, 256), 256>>>(N);
    k_count<<<cdiv(E, 256), 256>>>(ei32, E);
    k_scan<<<1, 1024>>>(N);
    k_fill<<<cdiv(E + N, 256), 256>>>(ei32, E, N);

    // layer 1: h1 = x @ W1 -> g_h ; agg -> g_feat
    dim3 g1(cdiv(H, BN), cdiv(N, BM));
    k_sgemm<<<g1, 256>>>(N, H, F, x, W1, 0, 0);
    k_score<<<cdiv(N, 8), 256>>>(as1, ad1, N, H);
    k_agg1<<<cdiv(N, 8), 256>>>(b1, N);

    // layer 2: h2 = g_feat @ W2 -> g_h ; agg+log_softmax -> d_out
    dim3 g2(cdiv(C, BN), cdiv(N, BM));
    k_sgemm<<<g2, 256>>>(N, C, H, nullptr, W2, 1, 0);
    k_score<<<cdiv(N, 8), 256>>>(as2, ad2, N, C);
    k_agg2<<<cdiv(N, 8), 256>>>(b2, (float*)d_out, N, C);
}

// round 9
// speedup vs baseline: 1.3487x; 1.3487x over previous
#include <cuda_runtime.h>
#include <math.h>

// ---------------- static scratch (no runtime allocation allowed) ------------
#define NMAX 100000
#define EMAX 1600000
#define ENMAX (EMAX + NMAX)
#define SCAN_CHUNK 1024
#define SCAN_MAXB ((NMAX + SCAN_CHUNK - 1) / SCAN_CHUNK)   // 98

__device__ float g_h[(size_t)NMAX * 128];     // h1 (layer1 GEMM out), reused as h2
__device__ float g_feat[(size_t)NMAX * 128];  // layer1 output features
__device__ float g_ss[NMAX];                  // per-node src score
__device__ float g_sd[NMAX];                  // per-node dst score
__device__ int   g_deg[NMAX];
__device__ int   g_rowptr[NMAX + 1];
__device__ int   g_cursor[NMAX];
__device__ int   g_srcidx[ENMAX];
__device__ int   g_is64;                      // edge_index dtype flag
__device__ int   g_part[SCAN_MAXB];           // per-block sums
__device__ int   g_partoff[SCAN_MAXB];        // exclusive-scanned block offsets

// ---------------- dtype probe ----------------------------------------------
// int64 indices < 2^31 have zero high words at all odd int32 positions.
__global__ void k_probe(const int* __restrict__ ei32) {
    if (threadIdx.x == 0 && blockIdx.x == 0) {
        int acc = ei32[1] | ei32[3] | ei32[5] | ei32[7] |
                  ei32[9] | ei32[11] | ei32[13] | ei32[15];
        g_is64 = (acc == 0) ? 1 : 0;
    }
}

__device__ __forceinline__ int load_src(const int* ei32, int E, int i) {
    int v = g_is64 ? ei32[2 * i] : ei32[i];
    return min(max(v, 0), NMAX - 1);
}
__device__ __forceinline__ int load_dst(const int* ei32, int E, int i) {
    int v = g_is64 ? ei32[2 * (E + i)] : ei32[E + i];
    return min(max(v, 0), NMAX - 1);
}

// ---------------- CSR build -------------------------------------------------
__global__ void k_initdeg(int N) {
    int i = blockIdx.x * blockDim.x + threadIdx.x;
    if (i < N) g_deg[i] = 1;  // self loop
}

__global__ void k_count(const int* __restrict__ ei32, int E) {
    int i = blockIdx.x * blockDim.x + threadIdx.x;
    if (i < E) atomicAdd(&g_deg[load_dst(ei32, E, i)], 1);
}

// ---- device-wide exclusive scan of g_deg -> g_rowptr/g_cursor, 3 phases ----
// phase 1: per-block sums (256 thr x 4 elem = 1024/block)
__global__ __launch_bounds__(256) void k_scan_blocksum(int n) {
    __shared__ int sh[256];
    int b = blockIdx.x, tid = threadIdx.x;
    int base = b * SCAN_CHUNK + tid * 4;
    int s = 0;
#pragma unroll
    for (int k = 0; k < 4; k++) {
        int i = base + k;
        if (i < n) s += g_deg[i];
    }
    sh[tid] = s;
    __syncthreads();
#pragma unroll
    for (int off = 128; off; off >>= 1) {
        if (tid < off) sh[tid] += sh[tid + off];
        __syncthreads();
    }
    if (tid == 0) g_part[b] = sh[0];
}

// phase 2: single small block scans the <=98 partials (exclusive)
__global__ void k_scan_partials(int nb, int n) {
    if (threadIdx.x == 0) {
        int run = 0;
        for (int b = 0; b < nb; b++) {
            g_partoff[b] = run;
            run += g_part[b];
        }
        g_rowptr[n] = run;  // total
    }
}

// phase 3: per-block local exclusive scan + base offset -> rowptr/cursor
__global__ __launch_bounds__(256) void k_scan_blockscan(int n) {
    __shared__ int sh[256];
    int b = blockIdx.x, tid = threadIdx.x;
    int base = b * SCAN_CHUNK + tid * 4;
    int v[4];
    int s = 0;
#pragma unroll
    for (int k = 0; k < 4; k++) {
        int i = base + k;
        v[k] = (i < n) ? g_deg[i] : 0;
        s += v[k];
    }
    sh[tid] = s;
    __syncthreads();
    // Hillis-Steele inclusive scan over thread sums
    for (int off = 1; off < 256; off <<= 1) {
        int t = (tid >= off) ? sh[tid - off] : 0;
        __syncthreads();
        sh[tid] += t;
        __syncthreads();
    }
    int run = g_partoff[b] + ((tid == 0) ? 0 : sh[tid - 1]);
#pragma unroll
    for (int k = 0; k < 4; k++) {
        int i = base + k;
        if (i < n) {
            g_rowptr[i] = run;
            g_cursor[i] = run;
            run += v[k];
        }
    }
}

__global__ void k_fill(const int* __restrict__ ei32, int E, int N) {
    int i = blockIdx.x * blockDim.x + threadIdx.x;
    if (i >= E + N) return;
    int s, d;
    if (i < E) {
        s = load_src(ei32, E, i);
        d = load_dst(ei32, E, i);
    } else {
        s = d = i - E;
    }
    int pos = atomicAdd(&g_cursor[d], 1);
    if (pos >= 0 && pos < ENMAX) g_srcidx[pos] = s;
}

// ---------------- SGEMM: C[M,N] = A[M,K] @ B[K,N], row major ---------------
// a_sel: 0 = external A pointer, 1 = g_feat ; c_sel: 0 = g_h, 1 = g_feat
#define BM 128
#define BN 128
#define BKK 8
#define TM 8
#define TN 8

__global__ __launch_bounds__(256) void k_sgemm(int M, int N, int K,
                                               const float* __restrict__ Aext,
                                               const float* __restrict__ B,
                                               int a_sel, int c_sel) {
    const float* A = (a_sel == 0) ? Aext : (const float*)g_feat;
    float* C = (c_sel == 0) ? g_h : g_feat;

    __shared__ __align__(16) float As[BKK][BM];
    __shared__ __align__(16) float Bs[BKK][BN];
    int tid = threadIdx.x;
    int rowBase = blockIdx.y * BM;
    int colBase = blockIdx.x * BN;
    int aRow = tid >> 1;
    int aCol = (tid & 1) << 2;
    int bRow = tid >> 5;
    int bCol = (tid & 31) << 2;
    int tr = (tid >> 4) * TM;
    int tc = (tid & 15) * TN;
    float acc[TM][TN];
#pragma unroll
    for (int i = 0; i < TM; i++)
#pragma unroll
        for (int j = 0; j < TN; j++) acc[i][j] = 0.f;

    for (int k0 = 0; k0 < K; k0 += BKK) {
        float4 av = make_float4(0.f, 0.f, 0.f, 0.f);
        int gr = rowBase + aRow;
        if (gr < M)
            av = *reinterpret_cast<const float4*>(&A[(size_t)gr * K + k0 + aCol]);
        As[aCol + 0][aRow] = av.x;
        As[aCol + 1][aRow] = av.y;
        As[aCol + 2][aRow] = av.z;
        As[aCol + 3][aRow] = av.w;

        float4 bv = make_float4(0.f, 0.f, 0.f, 0.f);
        int gc = colBase + bCol;
        const float* brow = &B[(size_t)(k0 + bRow) * N];
        if (gc + 3 < N) {
            bv = *reinterpret_cast<const float4*>(&brow[gc]);
        } else if (gc < N) {
            bv.x = brow[gc];
            if (gc + 1 < N) bv.y = brow[gc + 1];
            if (gc + 2 < N) bv.z = brow[gc + 2];
        }
        *reinterpret_cast<float4*>(&Bs[bRow][bCol]) = bv;
        __syncthreads();
#pragma unroll
        for (int k = 0; k < BKK; k++) {
            float ra[TM], rb[TN];
#pragma unroll
            for (int i = 0; i < TM; i++) ra[i] = As[k][tr + i];
#pragma unroll
            for (int j = 0; j < TN; j++) rb[j] = Bs[k][tc + j];
#pragma unroll
            for (int i = 0; i < TM; i++)
#pragma unroll
                for (int j = 0; j < TN; j++) acc[i][j] += ra[i] * rb[j];
        }
        __syncthreads();
    }
#pragma unroll
    for (int i = 0; i < TM; i++) {
        int r = rowBase + tr + i;
        if (r >= M) continue;
        float* crow = &C[(size_t)r * N];
#pragma unroll
        for (int j = 0; j < TN; j += 4) {
            int c = colBase + tc + j;
            if (c + 3 < N) {
                float4 v = make_float4(acc[i][j], acc[i][j + 1], acc[i][j + 2], acc[i][j + 3]);
                *reinterpret_cast<float4*>(&crow[c]) = v;
            } else {
#pragma unroll
                for (int jj = 0; jj < 4; jj++)
                    if (c + jj < N) crow[c + jj] = acc[i][j + jj];
            }
        }
    }
}

// ---------------- per-node attention scores: s = h . a ----------------------
__global__ __launch_bounds__(256) void k_score(const float* __restrict__ asrc,
                                               const float* __restrict__ adst,
                                               int N, int W) {
    int warp = (blockIdx.x * blockDim.x + threadIdx.x) >> 5;
    int lane = threadIdx.x & 31;
    if (warp >= N) return;
    const float* row = g_h + (size_t)warp * W;
    float s = 0.f, d = 0.f;
    for (int c = lane; c < W; c += 32) {
        float v = row[c];
        s += v * asrc[c];
        d += v * adst[c];
    }
#pragma unroll
    for (int o = 16; o; o >>= 1) {
        s += __shfl_xor_sync(0xffffffffu, s, o);
        d += __shfl_xor_sync(0xffffffffu, d, o);
    }
    if (lane == 0) {
        g_ss[warp] = s;
        g_sd[warp] = d;
    }
}

// ---------------- layer1 aggregation (H=128), fused bias+ReLU ---------------
// software-pipelined gather: next srcidx + next h row prefetched each iter
__global__ __launch_bounds__(256) void k_agg1(const float* __restrict__ bias, int N) {
    int warp = (blockIdx.x * blockDim.x + threadIdx.x) >> 5;
    int lane = threadIdx.x & 31;
    if (warp >= N) return;
    int rp = g_rowptr[warp], re = g_rowptr[warp + 1];
    float sd = g_sd[warp];
    float mx = -3.402823466e38f;
    for (int j = rp + lane; j < re; j += 32) {
        float e = g_ss[g_srcidx[j]] + sd;
        e = e > 0.f ? e : 0.2f * e;
        mx = fmaxf(mx, e);
    }
#pragma unroll
    for (int o = 16; o; o >>= 1) mx = fmaxf(mx, __shfl_xor_sync(0xffffffffu, mx, o));

    float4 acc = make_float4(0.f, 0.f, 0.f, 0.f);
    float denom = 0.f;
    int coff = lane << 2;
    int s_cur = (rp < re) ? g_srcidx[rp] : 0;
    float ss_cur = (rp < re) ? g_ss[s_cur] : 0.f;
    float4 hv_cur = (rp < re)
        ? *reinterpret_cast<const float4*>(&g_h[(size_t)s_cur * 128 + coff])
        : make_float4(0.f, 0.f, 0.f, 0.f);
    for (int j = rp; j < re; j++) {
        int s_nxt = 0; float ss_nxt = 0.f;
        float4 hv_nxt = make_float4(0.f, 0.f, 0.f, 0.f);
        if (j + 1 < re) {
            s_nxt = g_srcidx[j + 1];
            ss_nxt = g_ss[s_nxt];
            hv_nxt = *reinterpret_cast<const float4*>(&g_h[(size_t)s_nxt * 128 + coff]);
        }
        float e = ss_cur + sd;
        e = e > 0.f ? e : 0.2f * e;
        float ex = __expf(e - mx);
        denom += ex;
        acc.x += ex * hv_cur.x;
        acc.y += ex * hv_cur.y;
        acc.z += ex * hv_cur.z;
        acc.w += ex * hv_cur.w;
        ss_cur = ss_nxt;
        hv_cur = hv_nxt;
    }
    float inv = 1.f / denom;
    float4 o;
    o.x = fmaxf(fmaf(acc.x, inv, bias[coff + 0]), 0.f);
    o.y = fmaxf(fmaf(acc.y, inv, bias[coff + 1]), 0.f);
    o.z = fmaxf(fmaf(acc.z, inv, bias[coff + 2]), 0.f);
    o.w = fmaxf(fmaf(acc.w, inv, bias[coff + 3]), 0.f);
    *reinterpret_cast<float4*>(&g_feat[(size_t)warp * 128 + coff]) = o;
}

// ---------------- layer2 aggregation (C<=64) + fused log_softmax ------------
__global__ __launch_bounds__(256) void k_agg2(const float* __restrict__ bias,
                                              float* __restrict__ out, int N, int C) {
    int warp = (blockIdx.x * blockDim.x + threadIdx.x) >> 5;
    int lane = threadIdx.x & 31;
    if (warp >= N) return;
    int rp = g_rowptr[warp], re = g_rowptr[warp + 1];
    float sd = g_sd[warp];
    float mx = -3.402823466e38f;
    for (int j = rp + lane; j < re; j += 32) {
        float e = g_ss[g_srcidx[j]] + sd;
        e = e > 0.f ? e : 0.2f * e;
        mx = fmaxf(mx, e);
    }
#pragma unroll
    for (int o = 16; o; o >>= 1) mx = fmaxf(mx, __shfl_xor_sync(0xffffffffu, mx, o));

    int c0 = lane, c1 = lane + 32;
    bool v0ok = c0 < C, v1ok = c1 < C;
    float a0 = 0.f, a1 = 0.f, denom = 0.f;
    int s_cur = (rp < re) ? g_srcidx[rp] : 0;
    float ss_cur = (rp < re) ? g_ss[s_cur] : 0.f;
    float h0_cur = 0.f, h1_cur = 0.f;
    if (rp < re) {
        const float* hr = &g_h[(size_t)s_cur * C];
        if (v0ok) h0_cur = hr[c0];
        if (v1ok) h1_cur = hr[c1];
    }
    for (int j = rp; j < re; j++) {
        float ss_nxt = 0.f, h0_nxt = 0.f, h1_nxt = 0.f;
        if (j + 1 < re) {
            int s_nxt = g_srcidx[j + 1];
            ss_nxt = g_ss[s_nxt];
            const float* hr = &g_h[(size_t)s_nxt * C];
            if (v0ok) h0_nxt = hr[c0];
            if (v1ok) h1_nxt = hr[c1];
        }
        float e = ss_cur + sd;
        e = e > 0.f ? e : 0.2f * e;
        float ex = __expf(e - mx);
        denom += ex;
        a0 += ex * h0_cur;
        a1 += ex * h1_cur;
        ss_cur = ss_nxt;
        h0_cur = h0_nxt;
        h1_cur = h1_nxt;
    }
    float inv = 1.f / denom;
    float v0 = v0ok ? fmaf(a0, inv, bias[c0]) : -3.402823466e38f;
    float v1 = v1ok ? fmaf(a1, inv, bias[c1]) : -3.402823466e38f;
    float m2 = fmaxf(v0, v1);
#pragma unroll
    for (int o = 16; o; o >>= 1) m2 = fmaxf(m2, __shfl_xor_sync(0xffffffffu, m2, o));
    float se = (v0ok ? __expf(v0 - m2) : 0.f) + (v1ok ? __expf(v1 - m2) : 0.f);
#pragma unroll
    for (int o = 16; o; o >>= 1) se += __shfl_xor_sync(0xffffffffu, se, o);
    float lse = m2 + logf(se);
    if (v0ok) out[(size_t)warp * C + c0] = v0 - lse;
    if (v1ok) out[(size_t)warp * C + c1] = v1 - lse;
}

// ---------------- launcher --------------------------------------------------
static inline int cdiv(int a, int b) { return (a + b - 1) / b; }

extern "C" void kernel_launch(void* const* d_in, const int* in_sizes, int n_in,
                              void* d_out, int out_size) {
    const float* x   = (const float*)d_in[0];
    const int* ei32  = (const int*)d_in[1];   // edge_index (int32, or int64 detected on device)
    const float* W1  = (const float*)d_in[2];
    const float* as1 = (const float*)d_in[3];
    const float* ad1 = (const float*)d_in[4];
    const float* b1  = (const float*)d_in[5];
    const float* W2  = (const float*)d_in[6];
    const float* as2 = (const float*)d_in[7];
    const float* ad2 = (const float*)d_in[8];
    const float* b2  = (const float*)d_in[9];

    int H = in_sizes[3];
    int C = in_sizes[7];
    int F = in_sizes[2] / H;
    int N = in_sizes[0] / F;
    int E = in_sizes[1] / 2;   // element count / 2, dtype-invariant

    // dtype probe + CSR build (shared by both layers)
    k_probe<<<1, 32>>>(ei32);
    k_initdeg<<<cdiv(N, 256), 256>>>(N);
    k_count<<<cdiv(E, 256), 256>>>(ei32, E);
    int nb = cdiv(N, SCAN_CHUNK);
    k_scan_blocksum<<<nb, 256>>>(N);
    k_scan_partials<<<1, 32>>>(nb, N);
    k_scan_blockscan<<<nb, 256>>>(N);
    k_fill<<<cdiv(E + N, 256), 256>>>(ei32, E, N);

    // layer 1: h1 = x @ W1 -> g_h ; agg -> g_feat
    dim3 g1(cdiv(H, BN), cdiv(N, BM));
    k_sgemm<<<g1, 256>>>(N, H, F, x, W1, 0, 0);
    k_score<<<cdiv(N, 8), 256>>>(as1, ad1, N, H);
    k_agg1<<<cdiv(N, 8), 256>>>(b1, N);

    // layer 2: h2 = g_feat @ W2 -> g_h ; agg+log_softmax -> d_out
    dim3 g2(cdiv(C, BN), cdiv(N, BM));
    k_sgemm<<<g2, 256>>>(N, C, H, nullptr, W2, 1, 0);
    k_score<<<cdiv(N, 8), 256>>>(as2, ad2, N, C);
    k_agg2<<<cdiv(N, 8), 256>>>(b2, (float*)d_out, N, C);
}

// round 10
// speedup vs baseline: 1.9023x; 1.4105x over previous
#include <cuda_runtime.h>
#include <math.h>
#include <stdint.h>

// ---------------- static scratch (no runtime allocation allowed) ------------
#define NMAX 100000
#define EMAX 1600000
#define ENMAX (EMAX + NMAX)
#define SCAN_CHUNK 1024
#define SCAN_MAXB ((NMAX + SCAN_CHUNK - 1) / SCAN_CHUNK)   // 98

__device__ float g_h[(size_t)NMAX * 128];     // h1 (layer1 GEMM out), reused as h2
__device__ float g_feat[(size_t)NMAX * 128];  // layer1 output features
__device__ float g_ss[NMAX];                  // per-node src score
__device__ float g_sd[NMAX];                  // per-node dst score
__device__ int   g_deg[NMAX];
__device__ int   g_rowptr[NMAX + 1];
__device__ int   g_cursor[NMAX];
__device__ int   g_srcidx[ENMAX];
__device__ int   g_is64;                      // edge_index dtype flag
__device__ int   g_part[SCAN_MAXB];           // per-block sums
__device__ int   g_partoff[SCAN_MAXB];        // exclusive-scanned block offsets

// ---------------- dtype probe ----------------------------------------------
__global__ void k_probe(const int* __restrict__ ei32) {
    if (threadIdx.x == 0 && blockIdx.x == 0) {
        int acc = ei32[1] | ei32[3] | ei32[5] | ei32[7] |
                  ei32[9] | ei32[11] | ei32[13] | ei32[15];
        g_is64 = (acc == 0) ? 1 : 0;
    }
}

__device__ __forceinline__ int load_src(const int* ei32, int E, int i) {
    int v = g_is64 ? ei32[2 * i] : ei32[i];
    return min(max(v, 0), NMAX - 1);
}
__device__ __forceinline__ int load_dst(const int* ei32, int E, int i) {
    int v = g_is64 ? ei32[2 * (E + i)] : ei32[E + i];
    return min(max(v, 0), NMAX - 1);
}

// ---------------- CSR build -------------------------------------------------
__global__ void k_initdeg(int N) {
    int i = blockIdx.x * blockDim.x + threadIdx.x;
    if (i < N) g_deg[i] = 1;  // self loop
}

__global__ void k_count(const int* __restrict__ ei32, int E) {
    int i = blockIdx.x * blockDim.x + threadIdx.x;
    if (i < E) atomicAdd(&g_deg[load_dst(ei32, E, i)], 1);
}

__global__ __launch_bounds__(256) void k_scan_blocksum(int n) {
    __shared__ int sh[256];
    int b = blockIdx.x, tid = threadIdx.x;
    int base = b * SCAN_CHUNK + tid * 4;
    int s = 0;
#pragma unroll
    for (int k = 0; k < 4; k++) {
        int i = base + k;
        if (i < n) s += g_deg[i];
    }
    sh[tid] = s;
    __syncthreads();
#pragma unroll
    for (int off = 128; off; off >>= 1) {
        if (tid < off) sh[tid] += sh[tid + off];
        __syncthreads();
    }
    if (tid == 0) g_part[b] = sh[0];
}

__global__ void k_scan_partials(int nb, int n) {
    if (threadIdx.x == 0) {
        int run = 0;
        for (int b = 0; b < nb; b++) {
            g_partoff[b] = run;
            run += g_part[b];
        }
        g_rowptr[n] = run;
    }
}

__global__ __launch_bounds__(256) void k_scan_blockscan(int n) {
    __shared__ int sh[256];
    int b = blockIdx.x, tid = threadIdx.x;
    int base = b * SCAN_CHUNK + tid * 4;
    int v[4];
    int s = 0;
#pragma unroll
    for (int k = 0; k < 4; k++) {
        int i = base + k;
        v[k] = (i < n) ? g_deg[i] : 0;
        s += v[k];
    }
    sh[tid] = s;
    __syncthreads();
    for (int off = 1; off < 256; off <<= 1) {
        int t = (tid >= off) ? sh[tid - off] : 0;
        __syncthreads();
        sh[tid] += t;
        __syncthreads();
    }
    int run = g_partoff[b] + ((tid == 0) ? 0 : sh[tid - 1]);
#pragma unroll
    for (int k = 0; k < 4; k++) {
        int i = base + k;
        if (i < n) {
            g_rowptr[i] = run;
            g_cursor[i] = run;
            run += v[k];
        }
    }
}

__global__ void k_fill(const int* __restrict__ ei32, int E, int N) {
    int i = blockIdx.x * blockDim.x + threadIdx.x;
    if (i >= E + N) return;
    int s, d;
    if (i < E) {
        s = load_src(ei32, E, i);
        d = load_dst(ei32, E, i);
    } else {
        s = d = i - E;
    }
    int pos = atomicAdd(&g_cursor[d], 1);
    if (pos >= 0 && pos < ENMAX) g_srcidx[pos] = s;
}

// ---------------- TF32 tensor-core GEMM: g_h = A[M,K] @ B[K,Nn] -------------
// a_sel: 0 = external A, 1 = g_feat. Output always g_h (row stride Nn).
// CTA tile 128x128, BK=32. 8 warps (4 M x 2 N), warp tile 32x64,
// per warp 2x8 fragments of mma.m16n8k8.tf32, fp32 accumulate.
__device__ __forceinline__ uint32_t f2tf32(float f) {
    uint32_t u;
    asm("cvt.rna.tf32.f32 %0, %1;" : "=r"(u) : "f"(f));
    return u;
}

__device__ __forceinline__ void mma_tf32(float* c, uint32_t a0, uint32_t a1,
                                         uint32_t a2, uint32_t a3,
                                         uint32_t b0, uint32_t b1) {
    asm volatile(
        "mma.sync.aligned.m16n8k8.row.col.f32.tf32.tf32.f32 "
        "{%0,%1,%2,%3}, {%4,%5,%6,%7}, {%8,%9}, {%0,%1,%2,%3};"
        : "+f"(c[0]), "+f"(c[1]), "+f"(c[2]), "+f"(c[3])
        : "r"(a0), "r"(a1), "r"(a2), "r"(a3), "r"(b0), "r"(b1));
}

#define APAD 36   // 36 % 32 = 4  -> A-fragment banks 4m+k, conflict-free
#define BPAD 136  // 136 % 32 = 8 -> B-fragment banks 8k+n, conflict-free

__global__ __launch_bounds__(256, 2) void k_gemm_tf32(
    int M, int Nn, int K,
    const float* __restrict__ Aext, const float* __restrict__ B, int a_sel) {
    const float* A = (a_sel == 0) ? Aext : (const float*)g_feat;

    __shared__ uint32_t As[128][APAD];
    __shared__ uint32_t Bs[32][BPAD];

    int tid = threadIdx.x;
    int lane = tid & 31, wid = tid >> 5;
    int warp_m = wid & 3, warp_n = wid >> 2;
    int groupID = lane >> 2;    // 0..7
    int tig = lane & 3;         // 0..3
    int rowBase = blockIdx.y * 128;
    int colBase = blockIdx.x * 128;

    float acc[2][8][4];
#pragma unroll
    for (int i = 0; i < 2; i++)
#pragma unroll
        for (int j = 0; j < 8; j++)
#pragma unroll
            for (int q = 0; q < 4; q++) acc[i][j][q] = 0.f;

    int aRow = tid >> 1;          // 0..127
    int aSeg = (tid & 1) << 4;    // 0 / 16
    int bRow = tid >> 3;          // 0..31
    int bSeg = (tid & 7) << 4;    // 0..112

    for (int kk = 0; kk < K; kk += 32) {
        // ---- A tile: 128 x 32 ----
        {
            int gr = rowBase + aRow;
            const float* ap = A + (size_t)gr * K + kk + aSeg;
#pragma unroll
            for (int v = 0; v < 4; v++) {
                float4 f = (gr < M)
                    ? *reinterpret_cast<const float4*>(ap + v * 4)
                    : make_float4(0.f, 0.f, 0.f, 0.f);
                As[aRow][aSeg + v * 4 + 0] = f2tf32(f.x);
                As[aRow][aSeg + v * 4 + 1] = f2tf32(f.y);
                As[aRow][aSeg + v * 4 + 2] = f2tf32(f.z);
                As[aRow][aSeg + v * 4 + 3] = f2tf32(f.w);
            }
        }
        // ---- B tile: 32 x 128 (column-guarded for Nn < 128) ----
        {
            const float* bp = B + (size_t)(kk + bRow) * Nn + colBase + bSeg;
#pragma unroll
            for (int v = 0; v < 4; v++) {
                int c = colBase + bSeg + v * 4;
                float4 f;
                if (c + 3 < Nn) {
                    f = *reinterpret_cast<const float4*>(bp + v * 4);
                } else {
                    f = make_float4(0.f, 0.f, 0.f, 0.f);
                    if (c + 0 < Nn) f.x = bp[v * 4 + 0];
                    if (c + 1 < Nn) f.y = bp[v * 4 + 1];
                    if (c + 2 < Nn) f.z = bp[v * 4 + 2];
                }
                Bs[bRow][bSeg + v * 4 + 0] = f2tf32(f.x);
                Bs[bRow][bSeg + v * 4 + 1] = f2tf32(f.y);
                Bs[bRow][bSeg + v * 4 + 2] = f2tf32(f.z);
                Bs[bRow][bSeg + v * 4 + 3] = f2tf32(f.w);
            }
        }
        __syncthreads();
#pragma unroll
        for (int kt = 0; kt < 4; kt++) {
            int k = kt * 8;
            uint32_t b0[8], b1[8];
#pragma unroll
            for (int j = 0; j < 8; j++) {
                int n = warp_n * 64 + j * 8 + groupID;
                b0[j] = Bs[k + tig][n];
                b1[j] = Bs[k + tig + 4][n];
            }
#pragma unroll
            for (int i = 0; i < 2; i++) {
                int m = warp_m * 32 + i * 16;
                uint32_t a0 = As[m + groupID][k + tig];
                uint32_t a1 = As[m + 8 + groupID][k + tig];
                uint32_t a2 = As[m + groupID][k + 4 + tig];
                uint32_t a3 = As[m + 8 + groupID][k + 4 + tig];
#pragma unroll
                for (int j = 0; j < 8; j++)
                    mma_tf32(acc[i][j], a0, a1, a2, a3, b0[j], b1[j]);
            }
        }
        __syncthreads();
    }

    // ---- epilogue -> g_h ----
#pragma unroll
    for (int i = 0; i < 2; i++) {
        int r0 = rowBase + warp_m * 32 + i * 16 + groupID;
        int r1 = r0 + 8;
#pragma unroll
        for (int j = 0; j < 8; j++) {
            int c = colBase + warp_n * 64 + j * 8 + tig * 2;
            if (c + 1 < Nn) {
                if (r0 < M)
                    *reinterpret_cast<float2*>(&g_h[(size_t)r0 * Nn + c]) =
                        make_float2(acc[i][j][0], acc[i][j][1]);
                if (r1 < M)
                    *reinterpret_cast<float2*>(&g_h[(size_t)r1 * Nn + c]) =
                        make_float2(acc[i][j][2], acc[i][j][3]);
            } else if (c < Nn) {
                if (r0 < M) g_h[(size_t)r0 * Nn + c] = acc[i][j][0];
                if (r1 < M) g_h[(size_t)r1 * Nn + c] = acc[i][j][2];
            }
        }
    }
}

// ---------------- per-node attention scores: s = h . a ----------------------
__global__ __launch_bounds__(256) void k_score(const float* __restrict__ asrc,
                                               const float* __restrict__ adst,
                                               int N, int W) {
    int warp = (blockIdx.x * blockDim.x + threadIdx.x) >> 5;
    int lane = threadIdx.x & 31;
    if (warp >= N) return;
    const float* row = g_h + (size_t)warp * W;
    float s = 0.f, d = 0.f;
    for (int c = lane; c < W; c += 32) {
        float v = row[c];
        s += v * asrc[c];
        d += v * adst[c];
    }
#pragma unroll
    for (int o = 16; o; o >>= 1) {
        s += __shfl_xor_sync(0xffffffffu, s, o);
        d += __shfl_xor_sync(0xffffffffu, d, o);
    }
    if (lane == 0) {
        g_ss[warp] = s;
        g_sd[warp] = d;
    }
}

// ---------------- layer1 aggregation (H=128), fused bias+ReLU ---------------
__global__ __launch_bounds__(256) void k_agg1(const float* __restrict__ bias, int N) {
    int warp = (blockIdx.x * blockDim.x + threadIdx.x) >> 5;
    int lane = threadIdx.x & 31;
    if (warp >= N) return;
    int rp = g_rowptr[warp], re = g_rowptr[warp + 1];
    float sd = g_sd[warp];
    float mx = -3.402823466e38f;
    for (int j = rp + lane; j < re; j += 32) {
        float e = g_ss[g_srcidx[j]] + sd;
        e = e > 0.f ? e : 0.2f * e;
        mx = fmaxf(mx, e);
    }
#pragma unroll
    for (int o = 16; o; o >>= 1) mx = fmaxf(mx, __shfl_xor_sync(0xffffffffu, mx, o));

    float4 acc = make_float4(0.f, 0.f, 0.f, 0.f);
    float denom = 0.f;
    int coff = lane << 2;
    int s_cur = (rp < re) ? g_srcidx[rp] : 0;
    float ss_cur = (rp < re) ? g_ss[s_cur] : 0.f;
    float4 hv_cur = (rp < re)
        ? *reinterpret_cast<const float4*>(&g_h[(size_t)s_cur * 128 + coff])
        : make_float4(0.f, 0.f, 0.f, 0.f);
    for (int j = rp; j < re; j++) {
        int s_nxt = 0; float ss_nxt = 0.f;
        float4 hv_nxt = make_float4(0.f, 0.f, 0.f, 0.f);
        if (j + 1 < re) {
            s_nxt = g_srcidx[j + 1];
            ss_nxt = g_ss[s_nxt];
            hv_nxt = *reinterpret_cast<const float4*>(&g_h[(size_t)s_nxt * 128 + coff]);
        }
        float e = ss_cur + sd;
        e = e > 0.f ? e : 0.2f * e;
        float ex = __expf(e - mx);
        denom += ex;
        acc.x += ex * hv_cur.x;
        acc.y += ex * hv_cur.y;
        acc.z += ex * hv_cur.z;
        acc.w += ex * hv_cur.w;
        ss_cur = ss_nxt;
        hv_cur = hv_nxt;
    }
    float inv = 1.f / denom;
    float4 o;
    o.x = fmaxf(fmaf(acc.x, inv, bias[coff + 0]), 0.f);
    o.y = fmaxf(fmaf(acc.y, inv, bias[coff + 1]), 0.f);
    o.z = fmaxf(fmaf(acc.z, inv, bias[coff + 2]), 0.f);
    o.w = fmaxf(fmaf(acc.w, inv, bias[coff + 3]), 0.f);
    *reinterpret_cast<float4*>(&g_feat[(size_t)warp * 128 + coff]) = o;
}

// ---------------- layer2 aggregation (C<=64) + fused log_softmax ------------
__global__ __launch_bounds__(256) void k_agg2(const float* __restrict__ bias,
                                              float* __restrict__ out, int N, int C) {
    int warp = (blockIdx.x * blockDim.x + threadIdx.x) >> 5;
    int lane = threadIdx.x & 31;
    if (warp >= N) return;
    int rp = g_rowptr[warp], re = g_rowptr[warp + 1];
    float sd = g_sd[warp];
    float mx = -3.402823466e38f;
    for (int j = rp + lane; j < re; j += 32) {
        float e = g_ss[g_srcidx[j]] + sd;
        e = e > 0.f ? e : 0.2f * e;
        mx = fmaxf(mx, e);
    }
#pragma unroll
    for (int o = 16; o; o >>= 1) mx = fmaxf(mx, __shfl_xor_sync(0xffffffffu, mx, o));

    int c0 = lane, c1 = lane + 32;
    bool v0ok = c0 < C, v1ok = c1 < C;
    float a0 = 0.f, a1 = 0.f, denom = 0.f;
    int s_cur = (rp < re) ? g_srcidx[rp] : 0;
    float ss_cur = (rp < re) ? g_ss[s_cur] : 0.f;
    float h0_cur = 0.f, h1_cur = 0.f;
    if (rp < re) {
        const float* hr = &g_h[(size_t)s_cur * C];
        if (v0ok) h0_cur = hr[c0];
        if (v1ok) h1_cur = hr[c1];
    }
    for (int j = rp; j < re; j++) {
        float ss_nxt = 0.f, h0_nxt = 0.f, h1_nxt = 0.f;
        if (j + 1 < re) {
            int s_nxt = g_srcidx[j + 1];
            ss_nxt = g_ss[s_nxt];
            const float* hr = &g_h[(size_t)s_nxt * C];
            if (v0ok) h0_nxt = hr[c0];
            if (v1ok) h1_nxt = hr[c1];
        }
        float e = ss_cur + sd;
        e = e > 0.f ? e : 0.2f * e;
        float ex = __expf(e - mx);
        denom += ex;
        a0 += ex * h0_cur;
        a1 += ex * h1_cur;
        ss_cur = ss_nxt;
        h0_cur = h0_nxt;
        h1_cur = h1_nxt;
    }
    float inv = 1.f / denom;
    float v0 = v0ok ? fmaf(a0, inv, bias[c0]) : -3.402823466e38f;
    float v1 = v1ok ? fmaf(a1, inv, bias[c1]) : -3.402823466e38f;
    float m2 = fmaxf(v0, v1);
#pragma unroll
    for (int o = 16; o; o >>= 1) m2 = fmaxf(m2, __shfl_xor_sync(0xffffffffu, m2, o));
    float se = (v0ok ? __expf(v0 - m2) : 0.f) + (v1ok ? __expf(v1 - m2) : 0.f);
#pragma unroll
    for (int o = 16; o; o >>= 1) se += __shfl_xor_sync(0xffffffffu, se, o);
    float lse = m2 + logf(se);
    if (v0ok) out[(size_t)warp * C + c0] = v0 - lse;
    if (v1ok) out[(size_t)warp * C + c1] = v1 - lse;
}

// ---------------- launcher --------------------------------------------------
static inline int cdiv(int a, int b) { return (a + b - 1) / b; }

extern "C" void kernel_launch(void* const* d_in, const int* in_sizes, int n_in,
                              void* d_out, int out_size) {
    const float* x   = (const float*)d_in[0];
    const int* ei32  = (const int*)d_in[1];
    const float* W1  = (const float*)d_in[2];
    const float* as1 = (const float*)d_in[3];
    const float* ad1 = (const float*)d_in[4];
    const float* b1  = (const float*)d_in[5];
    const float* W2  = (const float*)d_in[6];
    const float* as2 = (const float*)d_in[7];
    const float* ad2 = (const float*)d_in[8];
    const float* b2  = (const float*)d_in[9];

    int H = in_sizes[3];
    int C = in_sizes[7];
    int F = in_sizes[2] / H;
    int N = in_sizes[0] / F;
    int E = in_sizes[1] / 2;

    // dtype probe + CSR build (shared by both layers)
    k_probe<<<1, 32>>>(ei32);
    k_initdeg<<<cdiv(N, 256), 256>>>(N);
    k_count<<<cdiv(E, 256), 256>>>(ei32, E);
    int nb = cdiv(N, SCAN_CHUNK);
    k_scan_blocksum<<<nb, 256>>>(N);
    k_scan_partials<<<1, 32>>>(nb, N);
    k_scan_blockscan<<<nb, 256>>>(N);
    k_fill<<<cdiv(E + N, 256), 256>>>(ei32, E, N);

    // layer 1: h1 = x @ W1 -> g_h (tf32 tensor cores) ; agg -> g_feat
    dim3 g1(cdiv(H, 128), cdiv(N, 128));
    k_gemm_tf32<<<g1, 256>>>(N, H, F, x, W1, 0);
    k_score<<<cdiv(N, 8), 256>>>(as1, ad1, N, H);
    k_agg1<<<cdiv(N, 8), 256>>>(b1, N);

    // layer 2: h2 = g_feat @ W2 -> g_h (tf32) ; agg+log_softmax -> d_out
    dim3 g2(cdiv(C, 128), cdiv(N, 128));
    k_gemm_tf32<<<g2, 256>>>(N, C, H, nullptr, W2, 1);
    k_score<<<cdiv(N, 8), 256>>>(as2, ad2, N, C);
    k_agg2<<<cdiv(N, 8), 256>>>(b2, (float*)d_out, N, C);
}

// round 11
// speedup vs baseline: 2.0389x; 1.0718x over previous
#include <cuda_runtime.h>
#include <math.h>
#include <stdint.h>

// ---------------- static scratch (no runtime allocation allowed) ------------
#define NMAX 100000
#define EMAX 1600000
#define ENMAX (EMAX + NMAX)
#define SCAN_CHUNK 1024
#define SCAN_MAXB ((NMAX + SCAN_CHUNK - 1) / SCAN_CHUNK)   // 98

__device__ float g_h[(size_t)NMAX * 128];     // h1 (layer1 GEMM out), reused as h2
__device__ float g_feat[(size_t)NMAX * 128];  // layer1 output features
__device__ float g_ss[NMAX];                  // per-node src score
__device__ float g_sd[NMAX];                  // per-node dst score
__device__ int   g_deg[NMAX];
__device__ int   g_rowptr[NMAX + 1];
__device__ int   g_cursor[NMAX];
__device__ int   g_srcidx[ENMAX];
__device__ int   g_is64;                      // edge_index dtype flag
__device__ int   g_part[SCAN_MAXB];
__device__ int   g_partoff[SCAN_MAXB];

// ---------------- dtype probe ----------------------------------------------
__global__ void k_probe(const int* __restrict__ ei32) {
    if (threadIdx.x == 0 && blockIdx.x == 0) {
        int acc = ei32[1] | ei32[3] | ei32[5] | ei32[7] |
                  ei32[9] | ei32[11] | ei32[13] | ei32[15];
        g_is64 = (acc == 0) ? 1 : 0;
    }
}

__device__ __forceinline__ int load_src(const int* ei32, int E, int i) {
    int v = g_is64 ? ei32[2 * i] : ei32[i];
    return min(max(v, 0), NMAX - 1);
}
__device__ __forceinline__ int load_dst(const int* ei32, int E, int i) {
    int v = g_is64 ? ei32[2 * (E + i)] : ei32[E + i];
    return min(max(v, 0), NMAX - 1);
}

// ---------------- CSR build -------------------------------------------------
__global__ void k_initdeg(int N) {
    int i = blockIdx.x * blockDim.x + threadIdx.x;
    if (i < N) g_deg[i] = 1;  // self loop
}

__global__ void k_count(const int* __restrict__ ei32, int E) {
    int i = blockIdx.x * blockDim.x + threadIdx.x;
    if (i < E) atomicAdd(&g_deg[load_dst(ei32, E, i)], 1);
}

__global__ __launch_bounds__(256) void k_scan_blocksum(int n) {
    __shared__ int sh[256];
    int b = blockIdx.x, tid = threadIdx.x;
    int base = b * SCAN_CHUNK + tid * 4;
    int s = 0;
#pragma unroll
    for (int k = 0; k < 4; k++) {
        int i = base + k;
        if (i < n) s += g_deg[i];
    }
    sh[tid] = s;
    __syncthreads();
#pragma unroll
    for (int off = 128; off; off >>= 1) {
        if (tid < off) sh[tid] += sh[tid + off];
        __syncthreads();
    }
    if (tid == 0) g_part[b] = sh[0];
}

__global__ void k_scan_partials(int nb, int n) {
    if (threadIdx.x == 0) {
        int run = 0;
        for (int b = 0; b < nb; b++) {
            g_partoff[b] = run;
            run += g_part[b];
        }
        g_rowptr[n] = run;
    }
}

__global__ __launch_bounds__(256) void k_scan_blockscan(int n) {
    __shared__ int sh[256];
    int b = blockIdx.x, tid = threadIdx.x;
    int base = b * SCAN_CHUNK + tid * 4;
    int v[4];
    int s = 0;
#pragma unroll
    for (int k = 0; k < 4; k++) {
        int i = base + k;
        v[k] = (i < n) ? g_deg[i] : 0;
        s += v[k];
    }
    sh[tid] = s;
    __syncthreads();
    for (int off = 1; off < 256; off <<= 1) {
        int t = (tid >= off) ? sh[tid - off] : 0;
        __syncthreads();
        sh[tid] += t;
        __syncthreads();
    }
    int run = g_partoff[b] + ((tid == 0) ? 0 : sh[tid - 1]);
#pragma unroll
    for (int k = 0; k < 4; k++) {
        int i = base + k;
        if (i < n) {
            g_rowptr[i] = run;
            g_cursor[i] = run;
            run += v[k];
        }
    }
}

__global__ void k_fill(const int* __restrict__ ei32, int E, int N) {
    int i = blockIdx.x * blockDim.x + threadIdx.x;
    if (i >= E + N) return;
    int s, d;
    if (i < E) {
        s = load_src(ei32, E, i);
        d = load_dst(ei32, E, i);
    } else {
        s = d = i - E;
    }
    int pos = atomicAdd(&g_cursor[d], 1);
    if (pos >= 0 && pos < ENMAX) g_srcidx[pos] = s;
}

// ---------------- TF32 tensor GEMM + fused score epilogue -------------------
// g_h = A[M,K] @ B[K,Nn]; if asrc != null (requires gridDim.x==1):
//   g_ss[r] = h[r,:].asrc ; g_sd[r] = h[r,:].adst
__device__ __forceinline__ uint32_t f2tf32(float f) {
    uint32_t u;
    asm("cvt.rna.tf32.f32 %0, %1;" : "=r"(u) : "f"(f));
    return u;
}

__device__ __forceinline__ void mma_tf32(float* c, uint32_t a0, uint32_t a1,
                                         uint32_t a2, uint32_t a3,
                                         uint32_t b0, uint32_t b1) {
    asm volatile(
        "mma.sync.aligned.m16n8k8.row.col.f32.tf32.tf32.f32 "
        "{%0,%1,%2,%3}, {%4,%5,%6,%7}, {%8,%9}, {%0,%1,%2,%3};"
        : "+f"(c[0]), "+f"(c[1]), "+f"(c[2]), "+f"(c[3])
        : "r"(a0), "r"(a1), "r"(a2), "r"(a3), "r"(b0), "r"(b1));
}

#define APAD 36
#define BPAD 136

__global__ __launch_bounds__(256, 2) void k_gemm_tf32(
    int M, int Nn, int K,
    const float* __restrict__ Aext, const float* __restrict__ B, int a_sel,
    const float* __restrict__ asrc, const float* __restrict__ adst) {
    const float* A = (a_sel == 0) ? Aext : (const float*)g_feat;

    __shared__ uint32_t As[128][APAD];
    __shared__ uint32_t Bs[32][BPAD];

    int tid = threadIdx.x;
    int lane = tid & 31, wid = tid >> 5;
    int warp_m = wid & 3, warp_n = wid >> 2;
    int groupID = lane >> 2;
    int tig = lane & 3;
    int rowBase = blockIdx.y * 128;
    int colBase = blockIdx.x * 128;

    float acc[2][8][4];
#pragma unroll
    for (int i = 0; i < 2; i++)
#pragma unroll
        for (int j = 0; j < 8; j++)
#pragma unroll
            for (int q = 0; q < 4; q++) acc[i][j][q] = 0.f;

    int aRow = tid >> 1;
    int aSeg = (tid & 1) << 4;
    int bRow = tid >> 3;
    int bSeg = (tid & 7) << 4;
    int gr = rowBase + aRow;
    bool aOk = gr < M;

    float4 av[4], bv[4];
    // ---- prologue: load tile 0 ----
    {
        const float* ap = A + (size_t)gr * K + aSeg;
#pragma unroll
        for (int v = 0; v < 4; v++)
            av[v] = aOk ? *reinterpret_cast<const float4*>(ap + v * 4)
                        : make_float4(0.f, 0.f, 0.f, 0.f);
        const float* bp = B + (size_t)bRow * Nn + colBase + bSeg;
#pragma unroll
        for (int v = 0; v < 4; v++) {
            int c = colBase + bSeg + v * 4;
            float4 f = make_float4(0.f, 0.f, 0.f, 0.f);
            if (c + 3 < Nn) f = *reinterpret_cast<const float4*>(bp + v * 4);
            else if (c < Nn) {
                f.x = bp[v * 4];
                if (c + 1 < Nn) f.y = bp[v * 4 + 1];
                if (c + 2 < Nn) f.z = bp[v * 4 + 2];
            }
            bv[v] = f;
        }
    }
#pragma unroll
    for (int v = 0; v < 4; v++) {
        As[aRow][aSeg + v * 4 + 0] = f2tf32(av[v].x);
        As[aRow][aSeg + v * 4 + 1] = f2tf32(av[v].y);
        As[aRow][aSeg + v * 4 + 2] = f2tf32(av[v].z);
        As[aRow][aSeg + v * 4 + 3] = f2tf32(av[v].w);
        Bs[bRow][bSeg + v * 4 + 0] = f2tf32(bv[v].x);
        Bs[bRow][bSeg + v * 4 + 1] = f2tf32(bv[v].y);
        Bs[bRow][bSeg + v * 4 + 2] = f2tf32(bv[v].z);
        Bs[bRow][bSeg + v * 4 + 3] = f2tf32(bv[v].w);
    }
    __syncthreads();

    for (int kk = 32; kk <= K; kk += 32) {
        bool more = kk < K;
        // ---- prefetch next tile into registers (overlaps with compute) ----
        if (more) {
            const float* ap = A + (size_t)gr * K + kk + aSeg;
#pragma unroll
            for (int v = 0; v < 4; v++)
                av[v] = aOk ? *reinterpret_cast<const float4*>(ap + v * 4)
                            : make_float4(0.f, 0.f, 0.f, 0.f);
            const float* bp = B + (size_t)(kk + bRow) * Nn + colBase + bSeg;
#pragma unroll
            for (int v = 0; v < 4; v++) {
                int c = colBase + bSeg + v * 4;
                float4 f = make_float4(0.f, 0.f, 0.f, 0.f);
                if (c + 3 < Nn) f = *reinterpret_cast<const float4*>(bp + v * 4);
                else if (c < Nn) {
                    f.x = bp[v * 4];
                    if (c + 1 < Nn) f.y = bp[v * 4 + 1];
                    if (c + 2 < Nn) f.z = bp[v * 4 + 2];
                }
                bv[v] = f;
            }
        }
        // ---- compute current tile from smem ----
#pragma unroll
        for (int kt = 0; kt < 4; kt++) {
            int k = kt * 8;
            uint32_t b0[8], b1[8];
#pragma unroll
            for (int j = 0; j < 8; j++) {
                int n = warp_n * 64 + j * 8 + groupID;
                b0[j] = Bs[k + tig][n];
                b1[j] = Bs[k + tig + 4][n];
            }
#pragma unroll
            for (int i = 0; i < 2; i++) {
                int m = warp_m * 32 + i * 16;
                uint32_t a0 = As[m + groupID][k + tig];
                uint32_t a1 = As[m + 8 + groupID][k + tig];
                uint32_t a2 = As[m + groupID][k + 4 + tig];
                uint32_t a3 = As[m + 8 + groupID][k + 4 + tig];
#pragma unroll
                for (int j = 0; j < 8; j++)
                    mma_tf32(acc[i][j], a0, a1, a2, a3, b0[j], b1[j]);
            }
        }
        __syncthreads();
        if (more) {
#pragma unroll
            for (int v = 0; v < 4; v++) {
                As[aRow][aSeg + v * 4 + 0] = f2tf32(av[v].x);
                As[aRow][aSeg + v * 4 + 1] = f2tf32(av[v].y);
                As[aRow][aSeg + v * 4 + 2] = f2tf32(av[v].z);
                As[aRow][aSeg + v * 4 + 3] = f2tf32(av[v].w);
                Bs[bRow][bSeg + v * 4 + 0] = f2tf32(bv[v].x);
                Bs[bRow][bSeg + v * 4 + 1] = f2tf32(bv[v].y);
                Bs[bRow][bSeg + v * 4 + 2] = f2tf32(bv[v].z);
                Bs[bRow][bSeg + v * 4 + 3] = f2tf32(bv[v].w);
            }
            __syncthreads();
        }
    }

    // ---- epilogue: write h ----
#pragma unroll
    for (int i = 0; i < 2; i++) {
        int r0 = rowBase + warp_m * 32 + i * 16 + groupID;
        int r1 = r0 + 8;
#pragma unroll
        for (int j = 0; j < 8; j++) {
            int c = colBase + warp_n * 64 + j * 8 + tig * 2;
            if (c + 1 < Nn) {
                if (r0 < M)
                    *reinterpret_cast<float2*>(&g_h[(size_t)r0 * Nn + c]) =
                        make_float2(acc[i][j][0], acc[i][j][1]);
                if (r1 < M)
                    *reinterpret_cast<float2*>(&g_h[(size_t)r1 * Nn + c]) =
                        make_float2(acc[i][j][2], acc[i][j][3]);
            } else if (c < Nn) {
                if (r0 < M) g_h[(size_t)r0 * Nn + c] = acc[i][j][0];
                if (r1 < M) g_h[(size_t)r1 * Nn + c] = acc[i][j][2];
            }
        }
    }

    // ---- fused scores (only valid when this CTA owns all Nn columns) ------
    if (asrc != nullptr) {
        float ps[2][2] = {{0.f, 0.f}, {0.f, 0.f}};
        float pd[2][2] = {{0.f, 0.f}, {0.f, 0.f}};
#pragma unroll
        for (int j = 0; j < 8; j++) {
            int c = warp_n * 64 + j * 8 + tig * 2;
            float a0 = (c < Nn) ? asrc[c] : 0.f;
            float a1 = (c + 1 < Nn) ? asrc[c + 1] : 0.f;
            float d0 = (c < Nn) ? adst[c] : 0.f;
            float d1 = (c + 1 < Nn) ? adst[c + 1] : 0.f;
#pragma unroll
            for (int i = 0; i < 2; i++) {
                ps[i][0] += acc[i][j][0] * a0 + acc[i][j][1] * a1;
                ps[i][1] += acc[i][j][2] * a0 + acc[i][j][3] * a1;
                pd[i][0] += acc[i][j][0] * d0 + acc[i][j][1] * d1;
                pd[i][1] += acc[i][j][2] * d0 + acc[i][j][3] * d1;
            }
        }
        // reduce over tig (lane bits 0..1)
#pragma unroll
        for (int off = 1; off <= 2; off <<= 1) {
#pragma unroll
            for (int i = 0; i < 2; i++)
#pragma unroll
                for (int hh = 0; hh < 2; hh++) {
                    ps[i][hh] += __shfl_xor_sync(0xffffffffu, ps[i][hh], off);
                    pd[i][hh] += __shfl_xor_sync(0xffffffffu, pd[i][hh], off);
                }
        }
        // combine across warp_n via smem (reuse As)
        float* sred = reinterpret_cast<float*>(&As[0][0]);  // [2][128] s, then d
        __syncthreads();
        if (tig == 0) {
#pragma unroll
            for (int i = 0; i < 2; i++)
#pragma unroll
                for (int hh = 0; hh < 2; hh++) {
                    int rl = warp_m * 32 + i * 16 + hh * 8 + groupID;
                    sred[warp_n * 128 + rl] = ps[i][hh];
                    sred[256 + warp_n * 128 + rl] = pd[i][hh];
                }
        }
        __syncthreads();
        if (tid < 128) {
            int r = rowBase + tid;
            if (r < M) {
                g_ss[r] = sred[tid] + sred[128 + tid];
                g_sd[r] = sred[256 + tid] + sred[384 + tid];
            }
        }
    }
}

// ---------------- layer1 aggregation (H=128), fused bias+ReLU ---------------
__global__ __launch_bounds__(256) void k_agg1(const float* __restrict__ bias, int N) {
    int warp = (blockIdx.x * blockDim.x + threadIdx.x) >> 5;
    int lane = threadIdx.x & 31;
    if (warp >= N) return;
    int rp = g_rowptr[warp], re = g_rowptr[warp + 1];
    float sd = g_sd[warp];
    float mx = -3.402823466e38f;
    for (int j = rp + lane; j < re; j += 32) {
        float e = g_ss[g_srcidx[j]] + sd;
        e = e > 0.f ? e : 0.2f * e;
        mx = fmaxf(mx, e);
    }
#pragma unroll
    for (int o = 16; o; o >>= 1) mx = fmaxf(mx, __shfl_xor_sync(0xffffffffu, mx, o));

    float4 acc = make_float4(0.f, 0.f, 0.f, 0.f);
    float denom = 0.f;
    int coff = lane << 2;
    int s_cur = (rp < re) ? g_srcidx[rp] : 0;
    float ss_cur = (rp < re) ? g_ss[s_cur] : 0.f;
    float4 hv_cur = (rp < re)
        ? *reinterpret_cast<const float4*>(&g_h[(size_t)s_cur * 128 + coff])
        : make_float4(0.f, 0.f, 0.f, 0.f);
    for (int j = rp; j < re; j++) {
        int s_nxt = 0; float ss_nxt = 0.f;
        float4 hv_nxt = make_float4(0.f, 0.f, 0.f, 0.f);
        if (j + 1 < re) {
            s_nxt = g_srcidx[j + 1];
            ss_nxt = g_ss[s_nxt];
            hv_nxt = *reinterpret_cast<const float4*>(&g_h[(size_t)s_nxt * 128 + coff]);
        }
        float e = ss_cur + sd;
        e = e > 0.f ? e : 0.2f * e;
        float ex = __expf(e - mx);
        denom += ex;
        acc.x += ex * hv_cur.x;
        acc.y += ex * hv_cur.y;
        acc.z += ex * hv_cur.z;
        acc.w += ex * hv_cur.w;
        ss_cur = ss_nxt;
        hv_cur = hv_nxt;
    }
    float inv = 1.f / denom;
    float4 o;
    o.x = fmaxf(fmaf(acc.x, inv, bias[coff + 0]), 0.f);
    o.y = fmaxf(fmaf(acc.y, inv, bias[coff + 1]), 0.f);
    o.z = fmaxf(fmaf(acc.z, inv, bias[coff + 2]), 0.f);
    o.w = fmaxf(fmaf(acc.w, inv, bias[coff + 3]), 0.f);
    *reinterpret_cast<float4*>(&g_feat[(size_t)warp * 128 + coff]) = o;
}

// ---------------- layer2 aggregation (C<=64) + fused log_softmax ------------
__global__ __launch_bounds__(256) void k_agg2(const float* __restrict__ bias,
                                              float* __restrict__ out, int N, int C) {
    int warp = (blockIdx.x * blockDim.x + threadIdx.x) >> 5;
    int lane = threadIdx.x & 31;
    if (warp >= N) return;
    int rp = g_rowptr[warp], re = g_rowptr[warp + 1];
    float sd = g_sd[warp];
    float mx = -3.402823466e38f;
    for (int j = rp + lane; j < re; j += 32) {
        float e = g_ss[g_srcidx[j]] + sd;
        e = e > 0.f ? e : 0.2f * e;
        mx = fmaxf(mx, e);
    }
#pragma unroll
    for (int o = 16; o; o >>= 1) mx = fmaxf(mx, __shfl_xor_sync(0xffffffffu, mx, o));

    int c0 = lane, c1 = lane + 32;
    bool v0ok = c0 < C, v1ok = c1 < C;
    float a0 = 0.f, a1 = 0.f, denom = 0.f;
    int s_cur = (rp < re) ? g_srcidx[rp] : 0;
    float ss_cur = (rp < re) ? g_ss[s_cur] : 0.f;
    float h0_cur = 0.f, h1_cur = 0.f;
    if (rp < re) {
        const float* hr = &g_h[(size_t)s_cur * C];
        if (v0ok) h0_cur = hr[c0];
        if (v1ok) h1_cur = hr[c1];
    }
    for (int j = rp; j < re; j++) {
        float ss_nxt = 0.f, h0_nxt = 0.f, h1_nxt = 0.f;
        if (j + 1 < re) {
            int s_nxt = g_srcidx[j + 1];
            ss_nxt = g_ss[s_nxt];
            const float* hr = &g_h[(size_t)s_nxt * C];
            if (v0ok) h0_nxt = hr[c0];
            if (v1ok) h1_nxt = hr[c1];
        }
        float e = ss_cur + sd;
        e = e > 0.f ? e : 0.2f * e;
        float ex = __expf(e - mx);
        denom += ex;
        a0 += ex * h0_cur;
        a1 += ex * h1_cur;
        ss_cur = ss_nxt;
        h0_cur = h0_nxt;
        h1_cur = h1_nxt;
    }
    float inv = 1.f / denom;
    float v0 = v0ok ? fmaf(a0, inv, bias[c0]) : -3.402823466e38f;
    float v1 = v1ok ? fmaf(a1, inv, bias[c1]) : -3.402823466e38f;
    float m2 = fmaxf(v0, v1);
#pragma unroll
    for (int o = 16; o; o >>= 1) m2 = fmaxf(m2, __shfl_xor_sync(0xffffffffu, m2, o));
    float se = (v0ok ? __expf(v0 - m2) : 0.f) + (v1ok ? __expf(v1 - m2) : 0.f);
#pragma unroll
    for (int o = 16; o; o >>= 1) se += __shfl_xor_sync(0xffffffffu, se, o);
    float lse = m2 + logf(se);
    if (v0ok) out[(size_t)warp * C + c0] = v0 - lse;
    if (v1ok) out[(size_t)warp * C + c1] = v1 - lse;
}

// ---------------- launcher --------------------------------------------------
static inline int cdiv(int a, int b) { return (a + b - 1) / b; }

extern "C" void kernel_launch(void* const* d_in, const int* in_sizes, int n_in,
                              void* d_out, int out_size) {
    const float* x   = (const float*)d_in[0];
    const int* ei32  = (const int*)d_in[1];
    const float* W1  = (const float*)d_in[2];
    const float* as1 = (const float*)d_in[3];
    const float* ad1 = (const float*)d_in[4];
    const float* b1  = (const float*)d_in[5];
    const float* W2  = (const float*)d_in[6];
    const float* as2 = (const float*)d_in[7];
    const float* ad2 = (const float*)d_in[8];
    const float* b2  = (const float*)d_in[9];

    int H = in_sizes[3];
    int C = in_sizes[7];
    int F = in_sizes[2] / H;
    int N = in_sizes[0] / F;
    int E = in_sizes[1] / 2;

    // dtype probe + CSR build (shared by both layers)
    k_probe<<<1, 32>>>(ei32);
    k_initdeg<<<cdiv(N, 256), 256>>>(N);
    k_count<<<cdiv(E, 256), 256>>>(ei32, E);
    int nb = cdiv(N, SCAN_CHUNK);
    k_scan_blocksum<<<nb, 256>>>(N);
    k_scan_partials<<<1, 32>>>(nb, N);
    k_scan_blockscan<<<nb, 256>>>(N);
    k_fill<<<cdiv(E + N, 256), 256>>>(ei32, E, N);

    // layer 1: h1 = x @ W1 -> g_h, scores fused (grid.x==1 since H<=128)
    dim3 g1(cdiv(H, 128), cdiv(N, 128));
    const float* s1 = (g1.x == 1) ? as1 : nullptr;
    k_gemm_tf32<<<g1, 256>>>(N, H, F, x, W1, 0, s1, ad1);
    k_agg1<<<cdiv(N, 8), 256>>>(b1, N);

    // layer 2: h2 = g_feat @ W2 -> g_h, scores fused (C<=128)
    dim3 g2(cdiv(C, 128), cdiv(N, 128));
    const float* s2 = (g2.x == 1) ? as2 : nullptr;
    k_gemm_tf32<<<g2, 256>>>(N, C, H, nullptr, W2, 1, s2, ad2);
    k_agg2<<<cdiv(N, 8), 256>>>(b2, (float*)d_out, N, C);
}

// round 12
// speedup vs baseline: 2.1464x; 1.0527x over previous
#include <cuda_runtime.h>
#include <math.h>
#include <stdint.h>

// ---------------- static scratch (no runtime allocation allowed) ------------
#define NMAX 100000
#define EMAX 1600000
#define ENMAX (EMAX + NMAX)
#define SCAN_CHUNK 1024
#define SCAN_MAXB ((NMAX + SCAN_CHUNK - 1) / SCAN_CHUNK)   // 98

__device__ float g_h[(size_t)NMAX * 128];     // h1 (layer1 GEMM out), reused as h2
__device__ float g_feat[(size_t)NMAX * 128];  // layer1 output features
__device__ float g_ss[NMAX];                  // per-node src score
__device__ float g_sd[NMAX];                  // per-node dst score
__device__ int   g_deg[NMAX];
__device__ int   g_rowptr[NMAX + 1];
__device__ int   g_cursor[NMAX];
__device__ int   g_srcidx[ENMAX];
__device__ int   g_is64;                      // edge_index dtype flag
__device__ int   g_part[SCAN_MAXB];
__device__ int   g_partoff[SCAN_MAXB];

__device__ __forceinline__ int load_src(const int* ei32, int E, int i) {
    int v = g_is64 ? ei32[2 * i] : ei32[i];
    return min(max(v, 0), NMAX - 1);
}
__device__ __forceinline__ int load_dst(const int* ei32, int E, int i) {
    int v = g_is64 ? ei32[2 * (E + i)] : ei32[E + i];
    return min(max(v, 0), NMAX - 1);
}

// ---------------- CSR build -------------------------------------------------
// probe folded in: int64 indices < 2^31 have zero high words at odd positions
__global__ void k_initdeg(const int* __restrict__ ei32, int N) {
    int i = blockIdx.x * blockDim.x + threadIdx.x;
    if (i == 0) {
        int acc = ei32[1] | ei32[3] | ei32[5] | ei32[7] |
                  ei32[9] | ei32[11] | ei32[13] | ei32[15];
        g_is64 = (acc == 0) ? 1 : 0;
    }
    if (i < N) g_deg[i] = 1;  // self loop
}

__global__ void k_count(const int* __restrict__ ei32, int E) {
    int i = blockIdx.x * blockDim.x + threadIdx.x;
    if (i < E) atomicAdd(&g_deg[load_dst(ei32, E, i)], 1);
}

__global__ __launch_bounds__(256) void k_scan_blocksum(int n) {
    __shared__ int sh[256];
    int b = blockIdx.x, tid = threadIdx.x;
    int base = b * SCAN_CHUNK + tid * 4;
    int s = 0;
#pragma unroll
    for (int k = 0; k < 4; k++) {
        int i = base + k;
        if (i < n) s += g_deg[i];
    }
    sh[tid] = s;
    __syncthreads();
#pragma unroll
    for (int off = 128; off; off >>= 1) {
        if (tid < off) sh[tid] += sh[tid + off];
        __syncthreads();
    }
    if (tid == 0) g_part[b] = sh[0];
}

__global__ void k_scan_partials(int nb, int n) {
    if (threadIdx.x == 0) {
        int run = 0;
        for (int b = 0; b < nb; b++) {
            g_partoff[b] = run;
            run += g_part[b];
        }
        g_rowptr[n] = run;
    }
}

__global__ __launch_bounds__(256) void k_scan_blockscan(int n) {
    __shared__ int sh[256];
    int b = blockIdx.x, tid = threadIdx.x;
    int base = b * SCAN_CHUNK + tid * 4;
    int v[4];
    int s = 0;
#pragma unroll
    for (int k = 0; k < 4; k++) {
        int i = base + k;
        v[k] = (i < n) ? g_deg[i] : 0;
        s += v[k];
    }
    sh[tid] = s;
    __syncthreads();
    for (int off = 1; off < 256; off <<= 1) {
        int t = (tid >= off) ? sh[tid - off] : 0;
        __syncthreads();
        sh[tid] += t;
        __syncthreads();
    }
    int run = g_partoff[b] + ((tid == 0) ? 0 : sh[tid - 1]);
#pragma unroll
    for (int k = 0; k < 4; k++) {
        int i = base + k;
        if (i < n) {
            g_rowptr[i] = run;
            g_cursor[i] = run;
            run += v[k];
        }
    }
}

__global__ void k_fill(const int* __restrict__ ei32, int E, int N) {
    int i = blockIdx.x * blockDim.x + threadIdx.x;
    if (i >= E + N) return;
    int s, d;
    if (i < E) {
        s = load_src(ei32, E, i);
        d = load_dst(ei32, E, i);
    } else {
        s = d = i - E;
    }
    int pos = atomicAdd(&g_cursor[d], 1);
    if (pos >= 0 && pos < ENMAX) g_srcidx[pos] = s;
}

// ---------------- TF32 tensor GEMM + fused score epilogue -------------------
__device__ __forceinline__ uint32_t f2tf32(float f) {
    uint32_t u;
    asm("cvt.rna.tf32.f32 %0, %1;" : "=r"(u) : "f"(f));
    return u;
}

__device__ __forceinline__ void mma_tf32(float* c, uint32_t a0, uint32_t a1,
                                         uint32_t a2, uint32_t a3,
                                         uint32_t b0, uint32_t b1) {
    asm volatile(
        "mma.sync.aligned.m16n8k8.row.col.f32.tf32.tf32.f32 "
        "{%0,%1,%2,%3}, {%4,%5,%6,%7}, {%8,%9}, {%0,%1,%2,%3};"
        : "+f"(c[0]), "+f"(c[1]), "+f"(c[2]), "+f"(c[3])
        : "r"(a0), "r"(a1), "r"(a2), "r"(a3), "r"(b0), "r"(b1));
}

#define APAD 36
#define BPAD 136

__global__ __launch_bounds__(256, 2) void k_gemm_tf32(
    int M, int Nn, int K,
    const float* __restrict__ Aext, const float* __restrict__ B, int a_sel,
    const float* __restrict__ asrc, const float* __restrict__ adst) {
    const float* A = (a_sel == 0) ? Aext : (const float*)g_feat;

    __shared__ uint32_t As[128][APAD];
    __shared__ uint32_t Bs[32][BPAD];

    int tid = threadIdx.x;
    int lane = tid & 31, wid = tid >> 5;
    int warp_m = wid & 3, warp_n = wid >> 2;
    int groupID = lane >> 2;
    int tig = lane & 3;
    int rowBase = blockIdx.y * 128;
    int colBase = blockIdx.x * 128;

    float acc[2][8][4];
#pragma unroll
    for (int i = 0; i < 2; i++)
#pragma unroll
        for (int j = 0; j < 8; j++)
#pragma unroll
            for (int q = 0; q < 4; q++) acc[i][j][q] = 0.f;

    int aRow = tid >> 1;
    int aSeg = (tid & 1) << 4;
    int bRow = tid >> 3;
    int bSeg = (tid & 7) << 4;
    int gr = rowBase + aRow;
    bool aOk = gr < M;

    float4 av[4], bv[4];
    // ---- prologue: load tile 0 ----
    {
        const float* ap = A + (size_t)gr * K + aSeg;
#pragma unroll
        for (int v = 0; v < 4; v++)
            av[v] = aOk ? *reinterpret_cast<const float4*>(ap + v * 4)
                        : make_float4(0.f, 0.f, 0.f, 0.f);
        const float* bp = B + (size_t)bRow * Nn + colBase + bSeg;
#pragma unroll
        for (int v = 0; v < 4; v++) {
            int c = colBase + bSeg + v * 4;
            float4 f = make_float4(0.f, 0.f, 0.f, 0.f);
            if (c + 3 < Nn) f = *reinterpret_cast<const float4*>(bp + v * 4);
            else if (c < Nn) {
                f.x = bp[v * 4];
                if (c + 1 < Nn) f.y = bp[v * 4 + 1];
                if (c + 2 < Nn) f.z = bp[v * 4 + 2];
            }
            bv[v] = f;
        }
    }
#pragma unroll
    for (int v = 0; v < 4; v++) {
        As[aRow][aSeg + v * 4 + 0] = f2tf32(av[v].x);
        As[aRow][aSeg + v * 4 + 1] = f2tf32(av[v].y);
        As[aRow][aSeg + v * 4 + 2] = f2tf32(av[v].z);
        As[aRow][aSeg + v * 4 + 3] = f2tf32(av[v].w);
        Bs[bRow][bSeg + v * 4 + 0] = f2tf32(bv[v].x);
        Bs[bRow][bSeg + v * 4 + 1] = f2tf32(bv[v].y);
        Bs[bRow][bSeg + v * 4 + 2] = f2tf32(bv[v].z);
        Bs[bRow][bSeg + v * 4 + 3] = f2tf32(bv[v].w);
    }
    __syncthreads();

    for (int kk = 32; kk <= K; kk += 32) {
        bool more = kk < K;
        if (more) {
            const float* ap = A + (size_t)gr * K + kk + aSeg;
#pragma unroll
            for (int v = 0; v < 4; v++)
                av[v] = aOk ? *reinterpret_cast<const float4*>(ap + v * 4)
                            : make_float4(0.f, 0.f, 0.f, 0.f);
            const float* bp = B + (size_t)(kk + bRow) * Nn + colBase + bSeg;
#pragma unroll
            for (int v = 0; v < 4; v++) {
                int c = colBase + bSeg + v * 4;
                float4 f = make_float4(0.f, 0.f, 0.f, 0.f);
                if (c + 3 < Nn) f = *reinterpret_cast<const float4*>(bp + v * 4);
                else if (c < Nn) {
                    f.x = bp[v * 4];
                    if (c + 1 < Nn) f.y = bp[v * 4 + 1];
                    if (c + 2 < Nn) f.z = bp[v * 4 + 2];
                }
                bv[v] = f;
            }
        }
#pragma unroll
        for (int kt = 0; kt < 4; kt++) {
            int k = kt * 8;
            uint32_t b0[8], b1[8];
#pragma unroll
            for (int j = 0; j < 8; j++) {
                int n = warp_n * 64 + j * 8 + groupID;
                b0[j] = Bs[k + tig][n];
                b1[j] = Bs[k + tig + 4][n];
            }
#pragma unroll
            for (int i = 0; i < 2; i++) {
                int m = warp_m * 32 + i * 16;
                uint32_t a0 = As[m + groupID][k + tig];
                uint32_t a1 = As[m + 8 + groupID][k + tig];
                uint32_t a2 = As[m + groupID][k + 4 + tig];
                uint32_t a3 = As[m + 8 + groupID][k + 4 + tig];
#pragma unroll
                for (int j = 0; j < 8; j++)
                    mma_tf32(acc[i][j], a0, a1, a2, a3, b0[j], b1[j]);
            }
        }
        __syncthreads();
        if (more) {
#pragma unroll
            for (int v = 0; v < 4; v++) {
                As[aRow][aSeg + v * 4 + 0] = f2tf32(av[v].x);
                As[aRow][aSeg + v * 4 + 1] = f2tf32(av[v].y);
                As[aRow][aSeg + v * 4 + 2] = f2tf32(av[v].z);
                As[aRow][aSeg + v * 4 + 3] = f2tf32(av[v].w);
                Bs[bRow][bSeg + v * 4 + 0] = f2tf32(bv[v].x);
                Bs[bRow][bSeg + v * 4 + 1] = f2tf32(bv[v].y);
                Bs[bRow][bSeg + v * 4 + 2] = f2tf32(bv[v].z);
                Bs[bRow][bSeg + v * 4 + 3] = f2tf32(bv[v].w);
            }
            __syncthreads();
        }
    }

    // ---- epilogue: write h ----
#pragma unroll
    for (int i = 0; i < 2; i++) {
        int r0 = rowBase + warp_m * 32 + i * 16 + groupID;
        int r1 = r0 + 8;
#pragma unroll
        for (int j = 0; j < 8; j++) {
            int c = colBase + warp_n * 64 + j * 8 + tig * 2;
            if (c + 1 < Nn) {
                if (r0 < M)
                    *reinterpret_cast<float2*>(&g_h[(size_t)r0 * Nn + c]) =
                        make_float2(acc[i][j][0], acc[i][j][1]);
                if (r1 < M)
                    *reinterpret_cast<float2*>(&g_h[(size_t)r1 * Nn + c]) =
                        make_float2(acc[i][j][2], acc[i][j][3]);
            } else if (c < Nn) {
                if (r0 < M) g_h[(size_t)r0 * Nn + c] = acc[i][j][0];
                if (r1 < M) g_h[(size_t)r1 * Nn + c] = acc[i][j][2];
            }
        }
    }

    // ---- fused scores (only valid when this CTA owns all Nn columns) ------
    if (asrc != nullptr) {
        float ps[2][2] = {{0.f, 0.f}, {0.f, 0.f}};
        float pd[2][2] = {{0.f, 0.f}, {0.f, 0.f}};
#pragma unroll
        for (int j = 0; j < 8; j++) {
            int c = warp_n * 64 + j * 8 + tig * 2;
            float a0 = (c < Nn) ? asrc[c] : 0.f;
            float a1 = (c + 1 < Nn) ? asrc[c + 1] : 0.f;
            float d0 = (c < Nn) ? adst[c] : 0.f;
            float d1 = (c + 1 < Nn) ? adst[c + 1] : 0.f;
#pragma unroll
            for (int i = 0; i < 2; i++) {
                ps[i][0] += acc[i][j][0] * a0 + acc[i][j][1] * a1;
                ps[i][1] += acc[i][j][2] * a0 + acc[i][j][3] * a1;
                pd[i][0] += acc[i][j][0] * d0 + acc[i][j][1] * d1;
                pd[i][1] += acc[i][j][2] * d0 + acc[i][j][3] * d1;
            }
        }
#pragma unroll
        for (int off = 1; off <= 2; off <<= 1) {
#pragma unroll
            for (int i = 0; i < 2; i++)
#pragma unroll
                for (int hh = 0; hh < 2; hh++) {
                    ps[i][hh] += __shfl_xor_sync(0xffffffffu, ps[i][hh], off);
                    pd[i][hh] += __shfl_xor_sync(0xffffffffu, pd[i][hh], off);
                }
        }
        float* sred = reinterpret_cast<float*>(&As[0][0]);
        __syncthreads();
        if (tig == 0) {
#pragma unroll
            for (int i = 0; i < 2; i++)
#pragma unroll
                for (int hh = 0; hh < 2; hh++) {
                    int rl = warp_m * 32 + i * 16 + hh * 8 + groupID;
                    sred[warp_n * 128 + rl] = ps[i][hh];
                    sred[256 + warp_n * 128 + rl] = pd[i][hh];
                }
        }
        __syncthreads();
        if (tid < 128) {
            int r = rowBase + tid;
            if (r < M) {
                g_ss[r] = sred[tid] + sred[128 + tid];
                g_sd[r] = sred[256 + tid] + sred[384 + tid];
            }
        }
    }
}

// ---------------- layer1 aggregation (H=128), fused bias+ReLU ---------------
__global__ __launch_bounds__(256) void k_agg1(const float* __restrict__ bias, int N) {
    int warp = (blockIdx.x * blockDim.x + threadIdx.x) >> 5;
    int lane = threadIdx.x & 31;
    if (warp >= N) return;
    int rp = g_rowptr[warp], re = g_rowptr[warp + 1];
    float sd = g_sd[warp];
    float mx = -3.402823466e38f;
    for (int j = rp + lane; j < re; j += 32) {
        float e = g_ss[g_srcidx[j]] + sd;
        e = e > 0.f ? e : 0.2f * e;
        mx = fmaxf(mx, e);
    }
#pragma unroll
    for (int o = 16; o; o >>= 1) mx = fmaxf(mx, __shfl_xor_sync(0xffffffffu, mx, o));

    float4 acc = make_float4(0.f, 0.f, 0.f, 0.f);
    float denom = 0.f;
    int coff = lane << 2;
    int s_cur = (rp < re) ? g_srcidx[rp] : 0;
    float ss_cur = (rp < re) ? g_ss[s_cur] : 0.f;
    float4 hv_cur = (rp < re)
        ? *reinterpret_cast<const float4*>(&g_h[(size_t)s_cur * 128 + coff])
        : make_float4(0.f, 0.f, 0.f, 0.f);
    for (int j = rp; j < re; j++) {
        int s_nxt = 0; float ss_nxt = 0.f;
        float4 hv_nxt = make_float4(0.f, 0.f, 0.f, 0.f);
        if (j + 1 < re) {
            s_nxt = g_srcidx[j + 1];
            ss_nxt = g_ss[s_nxt];
            hv_nxt = *reinterpret_cast<const float4*>(&g_h[(size_t)s_nxt * 128 + coff]);
        }
        float e = ss_cur + sd;
        e = e > 0.f ? e : 0.2f * e;
        float ex = __expf(e - mx);
        denom += ex;
        acc.x += ex * hv_cur.x;
        acc.y += ex * hv_cur.y;
        acc.z += ex * hv_cur.z;
        acc.w += ex * hv_cur.w;
        ss_cur = ss_nxt;
        hv_cur = hv_nxt;
    }
    float inv = 1.f / denom;
    float4 o;
    o.x = fmaxf(fmaf(acc.x, inv, bias[coff + 0]), 0.f);
    o.y = fmaxf(fmaf(acc.y, inv, bias[coff + 1]), 0.f);
    o.z = fmaxf(fmaf(acc.z, inv, bias[coff + 2]), 0.f);
    o.w = fmaxf(fmaf(acc.w, inv, bias[coff + 3]), 0.f);
    *reinterpret_cast<float4*>(&g_feat[(size_t)warp * 128 + coff]) = o;
}

// ---------------- layer2 aggregation (C<=64) + fused log_softmax ------------
__global__ __launch_bounds__(256) void k_agg2(const float* __restrict__ bias,
                                              float* __restrict__ out, int N, int C) {
    int warp = (blockIdx.x * blockDim.x + threadIdx.x) >> 5;
    int lane = threadIdx.x & 31;
    if (warp >= N) return;
    int rp = g_rowptr[warp], re = g_rowptr[warp + 1];
    float sd = g_sd[warp];
    float mx = -3.402823466e38f;
    for (int j = rp + lane; j < re; j += 32) {
        float e = g_ss[g_srcidx[j]] + sd;
        e = e > 0.f ? e : 0.2f * e;
        mx = fmaxf(mx, e);
    }
#pragma unroll
    for (int o = 16; o; o >>= 1) mx = fmaxf(mx, __shfl_xor_sync(0xffffffffu, mx, o));

    int c0 = lane, c1 = lane + 32;
    bool v0ok = c0 < C, v1ok = c1 < C;
    float a0 = 0.f, a1 = 0.f, denom = 0.f;
    int s_cur = (rp < re) ? g_srcidx[rp] : 0;
    float ss_cur = (rp < re) ? g_ss[s_cur] : 0.f;
    float h0_cur = 0.f, h1_cur = 0.f;
    if (rp < re) {
        const float* hr = &g_h[(size_t)s_cur * C];
        if (v0ok) h0_cur = hr[c0];
        if (v1ok) h1_cur = hr[c1];
    }
    for (int j = rp; j < re; j++) {
        float ss_nxt = 0.f, h0_nxt = 0.f, h1_nxt = 0.f;
        if (j + 1 < re) {
            int s_nxt = g_srcidx[j + 1];
            ss_nxt = g_ss[s_nxt];
            const float* hr = &g_h[(size_t)s_nxt * C];
            if (v0ok) h0_nxt = hr[c0];
            if (v1ok) h1_nxt = hr[c1];
        }
        float e = ss_cur + sd;
        e = e > 0.f ? e : 0.2f * e;
        float ex = __expf(e - mx);
        denom += ex;
        a0 += ex * h0_cur;
        a1 += ex * h1_cur;
        ss_cur = ss_nxt;
        h0_cur = h0_nxt;
        h1_cur = h1_nxt;
    }
    float inv = 1.f / denom;
    float v0 = v0ok ? fmaf(a0, inv, bias[c0]) : -3.402823466e38f;
    float v1 = v1ok ? fmaf(a1, inv, bias[c1]) : -3.402823466e38f;
    float m2 = fmaxf(v0, v1);
#pragma unroll
    for (int o = 16; o; o >>= 1) m2 = fmaxf(m2, __shfl_xor_sync(0xffffffffu, m2, o));
    float se = (v0ok ? __expf(v0 - m2) : 0.f) + (v1ok ? __expf(v1 - m2) : 0.f);
#pragma unroll
    for (int o = 16; o; o >>= 1) se += __shfl_xor_sync(0xffffffffu, se, o);
    float lse = m2 + logf(se);
    if (v0ok) out[(size_t)warp * C + c0] = v0 - lse;
    if (v1ok) out[(size_t)warp * C + c1] = v1 - lse;
}

// ---------------- launcher --------------------------------------------------
static inline int cdiv(int a, int b) { return (a + b - 1) / b; }

extern "C" void kernel_launch(void* const* d_in, const int* in_sizes, int n_in,
                              void* d_out, int out_size) {
    const float* x   = (const float*)d_in[0];
    const int* ei32  = (const int*)d_in[1];
    const float* W1  = (const float*)d_in[2];
    const float* as1 = (const float*)d_in[3];
    const float* ad1 = (const float*)d_in[4];
    const float* b1  = (const float*)d_in[5];
    const float* W2  = (const float*)d_in[6];
    const float* as2 = (const float*)d_in[7];
    const float* ad2 = (const float*)d_in[8];
    const float* b2  = (const float*)d_in[9];

    int H = in_sizes[3];
    int C = in_sizes[7];
    int F = in_sizes[2] / H;
    int N = in_sizes[0] / F;
    int E = in_sizes[1] / 2;

    // side stream + fork/join events: created once on first call (outside
    // capture), reused so every captured graph is identical.
    static cudaStream_t side = nullptr;
    static cudaEvent_t evFork = nullptr, evJoin = nullptr;
    if (side == nullptr) {
        cudaStreamCreateWithFlags(&side, cudaStreamNonBlocking);
        cudaEventCreateWithFlags(&evFork, cudaEventDisableTiming);
        cudaEventCreateWithFlags(&evJoin, cudaEventDisableTiming);
    }

    // fork: CSR build chain runs on side stream, concurrent with GEMM1
    cudaEventRecord(evFork, 0);
    cudaStreamWaitEvent(side, evFork, 0);

    int nb = cdiv(N, SCAN_CHUNK);
    k_initdeg<<<cdiv(N, 256), 256, 0, side>>>(ei32, N);
    k_count<<<cdiv(E, 256), 256, 0, side>>>(ei32, E);
    k_scan_blocksum<<<nb, 256, 0, side>>>(N);
    k_scan_partials<<<1, 32, 0, side>>>(nb, N);
    k_scan_blockscan<<<nb, 256, 0, side>>>(N);
    k_fill<<<cdiv(E + N, 256), 256, 0, side>>>(ei32, E, N);

    // layer 1 GEMM (+fused scores) on main stream, overlapped with CSR build
    dim3 g1(cdiv(H, 128), cdiv(N, 128));
    const float* s1 = (g1.x == 1) ? as1 : nullptr;
    k_gemm_tf32<<<g1, 256>>>(N, H, F, x, W1, 0, s1, ad1);

    // join: agg1 needs both CSR and GEMM1 results
    cudaEventRecord(evJoin, side);
    cudaStreamWaitEvent(0, evJoin, 0);

    k_agg1<<<cdiv(N, 8), 256>>>(b1, N);

    // layer 2: h2 = g_feat @ W2 -> g_h, scores fused; agg+log_softmax -> out
    dim3 g2(cdiv(C, 128), cdiv(N, 128));
    const float* s2 = (g2.x == 1) ? as2 : nullptr;
    k_gemm_tf32<<<g2, 256>>>(N, C, H, nullptr, W2, 1, s2, ad2);
    k_agg2<<<cdiv(N, 8), 256>>>(b2, (float*)d_out, N, C);
}

// round 13
// speedup vs baseline: 2.1561x; 1.0045x over previous
#include <cuda_runtime.h>
#include <cuda_fp16.h>
#include <math.h>
#include <stdint.h>

// ---------------- static scratch (no runtime allocation allowed) ------------
#define NMAX 100000
#define EMAX 1600000
#define ENMAX (EMAX + NMAX)
#define SCAN_CHUNK 1024
#define SCAN_MAXB ((NMAX + SCAN_CHUNK - 1) / SCAN_CHUNK)   // 98

__device__ __half g_hh[(size_t)NMAX * 128];   // h (fp16) — gather payload
__device__ float g_feat[(size_t)NMAX * 128];  // layer1 output features (fp32, GEMM2 A)
__device__ float g_ss[NMAX];                  // per-node src score
__device__ float g_sd[NMAX];                  // per-node dst score
__device__ int   g_deg[NMAX];
__device__ int   g_rowptr[NMAX + 1];
__device__ int   g_cursor[NMAX];
__device__ int   g_srcidx[ENMAX];
__device__ int   g_is64;                      // edge_index dtype flag
__device__ int   g_part[SCAN_MAXB];
__device__ int   g_partoff[SCAN_MAXB];

__device__ __forceinline__ int load_src(const int* ei32, int E, int i) {
    int v = g_is64 ? ei32[2 * i] : ei32[i];
    return min(max(v, 0), NMAX - 1);
}
__device__ __forceinline__ int load_dst(const int* ei32, int E, int i) {
    int v = g_is64 ? ei32[2 * (E + i)] : ei32[E + i];
    return min(max(v, 0), NMAX - 1);
}

// ---------------- CSR build -------------------------------------------------
__global__ void k_initdeg(const int* __restrict__ ei32, int N) {
    int i = blockIdx.x * blockDim.x + threadIdx.x;
    if (i == 0) {
        int acc = ei32[1] | ei32[3] | ei32[5] | ei32[7] |
                  ei32[9] | ei32[11] | ei32[13] | ei32[15];
        g_is64 = (acc == 0) ? 1 : 0;
    }
    if (i < N) g_deg[i] = 1;  // self loop
}

__global__ void k_count(const int* __restrict__ ei32, int E) {
    int i = blockIdx.x * blockDim.x + threadIdx.x;
    if (i < E) atomicAdd(&g_deg[load_dst(ei32, E, i)], 1);
}

__global__ __launch_bounds__(256) void k_scan_blocksum(int n) {
    __shared__ int sh[256];
    int b = blockIdx.x, tid = threadIdx.x;
    int base = b * SCAN_CHUNK + tid * 4;
    int s = 0;
#pragma unroll
    for (int k = 0; k < 4; k++) {
        int i = base + k;
        if (i < n) s += g_deg[i];
    }
    sh[tid] = s;
    __syncthreads();
#pragma unroll
    for (int off = 128; off; off >>= 1) {
        if (tid < off) sh[tid] += sh[tid + off];
        __syncthreads();
    }
    if (tid == 0) g_part[b] = sh[0];
}

__global__ void k_scan_partials(int nb, int n) {
    if (threadIdx.x == 0) {
        int run = 0;
        for (int b = 0; b < nb; b++) {
            g_partoff[b] = run;
            run += g_part[b];
        }
        g_rowptr[n] = run;
    }
}

__global__ __launch_bounds__(256) void k_scan_blockscan(int n) {
    __shared__ int sh[256];
    int b = blockIdx.x, tid = threadIdx.x;
    int base = b * SCAN_CHUNK + tid * 4;
    int v[4];
    int s = 0;
#pragma unroll
    for (int k = 0; k < 4; k++) {
        int i = base + k;
        v[k] = (i < n) ? g_deg[i] : 0;
        s += v[k];
    }
    sh[tid] = s;
    __syncthreads();
    for (int off = 1; off < 256; off <<= 1) {
        int t = (tid >= off) ? sh[tid - off] : 0;
        __syncthreads();
        sh[tid] += t;
        __syncthreads();
    }
    int run = g_partoff[b] + ((tid == 0) ? 0 : sh[tid - 1]);
#pragma unroll
    for (int k = 0; k < 4; k++) {
        int i = base + k;
        if (i < n) {
            g_rowptr[i] = run;
            g_cursor[i] = run;
            run += v[k];
        }
    }
}

__global__ void k_fill(const int* __restrict__ ei32, int E, int N) {
    int i = blockIdx.x * blockDim.x + threadIdx.x;
    if (i >= E + N) return;
    int s, d;
    if (i < E) {
        s = load_src(ei32, E, i);
        d = load_dst(ei32, E, i);
    } else {
        s = d = i - E;
    }
    int pos = atomicAdd(&g_cursor[d], 1);
    if (pos >= 0 && pos < ENMAX) g_srcidx[pos] = s;
}

// ---------------- TF32 tensor GEMM + fused score epilogue -------------------
// writes h as fp16 into g_hh; scores (fp32, from accs) into g_ss/g_sd
__device__ __forceinline__ uint32_t f2tf32(float f) {
    uint32_t u;
    asm("cvt.rna.tf32.f32 %0, %1;" : "=r"(u) : "f"(f));
    return u;
}

__device__ __forceinline__ void mma_tf32(float* c, uint32_t a0, uint32_t a1,
                                         uint32_t a2, uint32_t a3,
                                         uint32_t b0, uint32_t b1) {
    asm volatile(
        "mma.sync.aligned.m16n8k8.row.col.f32.tf32.tf32.f32 "
        "{%0,%1,%2,%3}, {%4,%5,%6,%7}, {%8,%9}, {%0,%1,%2,%3};"
        : "+f"(c[0]), "+f"(c[1]), "+f"(c[2]), "+f"(c[3])
        : "r"(a0), "r"(a1), "r"(a2), "r"(a3), "r"(b0), "r"(b1));
}

#define APAD 36
#define BPAD 136

__global__ __launch_bounds__(256, 2) void k_gemm_tf32(
    int M, int Nn, int K,
    const float* __restrict__ Aext, const float* __restrict__ B, int a_sel,
    const float* __restrict__ asrc, const float* __restrict__ adst) {
    const float* A = (a_sel == 0) ? Aext : (const float*)g_feat;

    __shared__ uint32_t As[128][APAD];
    __shared__ uint32_t Bs[32][BPAD];

    int tid = threadIdx.x;
    int lane = tid & 31, wid = tid >> 5;
    int warp_m = wid & 3, warp_n = wid >> 2;
    int groupID = lane >> 2;
    int tig = lane & 3;
    int rowBase = blockIdx.y * 128;
    int colBase = blockIdx.x * 128;

    float acc[2][8][4];
#pragma unroll
    for (int i = 0; i < 2; i++)
#pragma unroll
        for (int j = 0; j < 8; j++)
#pragma unroll
            for (int q = 0; q < 4; q++) acc[i][j][q] = 0.f;

    int aRow = tid >> 1;
    int aSeg = (tid & 1) << 4;
    int bRow = tid >> 3;
    int bSeg = (tid & 7) << 4;
    int gr = rowBase + aRow;
    bool aOk = gr < M;

    float4 av[4], bv[4];
    // ---- prologue: load tile 0 ----
    {
        const float* ap = A + (size_t)gr * K + aSeg;
#pragma unroll
        for (int v = 0; v < 4; v++)
            av[v] = aOk ? *reinterpret_cast<const float4*>(ap + v * 4)
                        : make_float4(0.f, 0.f, 0.f, 0.f);
        const float* bp = B + (size_t)bRow * Nn + colBase + bSeg;
#pragma unroll
        for (int v = 0; v < 4; v++) {
            int c = colBase + bSeg + v * 4;
            float4 f = make_float4(0.f, 0.f, 0.f, 0.f);
            if (c + 3 < Nn) f = *reinterpret_cast<const float4*>(bp + v * 4);
            else if (c < Nn) {
                f.x = bp[v * 4];
                if (c + 1 < Nn) f.y = bp[v * 4 + 1];
                if (c + 2 < Nn) f.z = bp[v * 4 + 2];
            }
            bv[v] = f;
        }
    }
#pragma unroll
    for (int v = 0; v < 4; v++) {
        As[aRow][aSeg + v * 4 + 0] = f2tf32(av[v].x);
        As[aRow][aSeg + v * 4 + 1] = f2tf32(av[v].y);
        As[aRow][aSeg + v * 4 + 2] = f2tf32(av[v].z);
        As[aRow][aSeg + v * 4 + 3] = f2tf32(av[v].w);
        Bs[bRow][bSeg + v * 4 + 0] = f2tf32(bv[v].x);
        Bs[bRow][bSeg + v * 4 + 1] = f2tf32(bv[v].y);
        Bs[bRow][bSeg + v * 4 + 2] = f2tf32(bv[v].z);
        Bs[bRow][bSeg + v * 4 + 3] = f2tf32(bv[v].w);
    }
    __syncthreads();

    for (int kk = 32; kk <= K; kk += 32) {
        bool more = kk < K;
        if (more) {
            const float* ap = A + (size_t)gr * K + kk + aSeg;
#pragma unroll
            for (int v = 0; v < 4; v++)
                av[v] = aOk ? *reinterpret_cast<const float4*>(ap + v * 4)
                            : make_float4(0.f, 0.f, 0.f, 0.f);
            const float* bp = B + (size_t)(kk + bRow) * Nn + colBase + bSeg;
#pragma unroll
            for (int v = 0; v < 4; v++) {
                int c = colBase + bSeg + v * 4;
                float4 f = make_float4(0.f, 0.f, 0.f, 0.f);
                if (c + 3 < Nn) f = *reinterpret_cast<const float4*>(bp + v * 4);
                else if (c < Nn) {
                    f.x = bp[v * 4];
                    if (c + 1 < Nn) f.y = bp[v * 4 + 1];
                    if (c + 2 < Nn) f.z = bp[v * 4 + 2];
                }
                bv[v] = f;
            }
        }
#pragma unroll
        for (int kt = 0; kt < 4; kt++) {
            int k = kt * 8;
            uint32_t b0[8], b1[8];
#pragma unroll
            for (int j = 0; j < 8; j++) {
                int n = warp_n * 64 + j * 8 + groupID;
                b0[j] = Bs[k + tig][n];
                b1[j] = Bs[k + tig + 4][n];
            }
#pragma unroll
            for (int i = 0; i < 2; i++) {
                int m = warp_m * 32 + i * 16;
                uint32_t a0 = As[m + groupID][k + tig];
                uint32_t a1 = As[m + 8 + groupID][k + tig];
                uint32_t a2 = As[m + groupID][k + 4 + tig];
                uint32_t a3 = As[m + 8 + groupID][k + 4 + tig];
#pragma unroll
                for (int j = 0; j < 8; j++)
                    mma_tf32(acc[i][j], a0, a1, a2, a3, b0[j], b1[j]);
            }
        }
        __syncthreads();
        if (more) {
#pragma unroll
            for (int v = 0; v < 4; v++) {
                As[aRow][aSeg + v * 4 + 0] = f2tf32(av[v].x);
                As[aRow][aSeg + v * 4 + 1] = f2tf32(av[v].y);
                As[aRow][aSeg + v * 4 + 2] = f2tf32(av[v].z);
                As[aRow][aSeg + v * 4 + 3] = f2tf32(av[v].w);
                Bs[bRow][bSeg + v * 4 + 0] = f2tf32(bv[v].x);
                Bs[bRow][bSeg + v * 4 + 1] = f2tf32(bv[v].y);
                Bs[bRow][bSeg + v * 4 + 2] = f2tf32(bv[v].z);
                Bs[bRow][bSeg + v * 4 + 3] = f2tf32(bv[v].w);
            }
            __syncthreads();
        }
    }

    // ---- epilogue: write h as fp16 (half2 stores) ----
#pragma unroll
    for (int i = 0; i < 2; i++) {
        int r0 = rowBase + warp_m * 32 + i * 16 + groupID;
        int r1 = r0 + 8;
#pragma unroll
        for (int j = 0; j < 8; j++) {
            int c = colBase + warp_n * 64 + j * 8 + tig * 2;
            if (c + 1 < Nn) {
                if (r0 < M)
                    *reinterpret_cast<__half2*>(&g_hh[(size_t)r0 * Nn + c]) =
                        __floats2half2_rn(acc[i][j][0], acc[i][j][1]);
                if (r1 < M)
                    *reinterpret_cast<__half2*>(&g_hh[(size_t)r1 * Nn + c]) =
                        __floats2half2_rn(acc[i][j][2], acc[i][j][3]);
            } else if (c < Nn) {
                if (r0 < M) g_hh[(size_t)r0 * Nn + c] = __float2half_rn(acc[i][j][0]);
                if (r1 < M) g_hh[(size_t)r1 * Nn + c] = __float2half_rn(acc[i][j][2]);
            }
        }
    }

    // ---- fused scores (fp32, from accumulators; requires gridDim.x==1) ----
    if (asrc != nullptr) {
        float ps[2][2] = {{0.f, 0.f}, {0.f, 0.f}};
        float pd[2][2] = {{0.f, 0.f}, {0.f, 0.f}};
#pragma unroll
        for (int j = 0; j < 8; j++) {
            int c = warp_n * 64 + j * 8 + tig * 2;
            float a0 = (c < Nn) ? asrc[c] : 0.f;
            float a1 = (c + 1 < Nn) ? asrc[c + 1] : 0.f;
            float d0 = (c < Nn) ? adst[c] : 0.f;
            float d1 = (c + 1 < Nn) ? adst[c + 1] : 0.f;
#pragma unroll
            for (int i = 0; i < 2; i++) {
                ps[i][0] += acc[i][j][0] * a0 + acc[i][j][1] * a1;
                ps[i][1] += acc[i][j][2] * a0 + acc[i][j][3] * a1;
                pd[i][0] += acc[i][j][0] * d0 + acc[i][j][1] * d1;
                pd[i][1] += acc[i][j][2] * d0 + acc[i][j][3] * d1;
            }
        }
#pragma unroll
        for (int off = 1; off <= 2; off <<= 1) {
#pragma unroll
            for (int i = 0; i < 2; i++)
#pragma unroll
                for (int hh = 0; hh < 2; hh++) {
                    ps[i][hh] += __shfl_xor_sync(0xffffffffu, ps[i][hh], off);
                    pd[i][hh] += __shfl_xor_sync(0xffffffffu, pd[i][hh], off);
                }
        }
        float* sred = reinterpret_cast<float*>(&As[0][0]);
        __syncthreads();
        if (tig == 0) {
#pragma unroll
            for (int i = 0; i < 2; i++)
#pragma unroll
                for (int hh = 0; hh < 2; hh++) {
                    int rl = warp_m * 32 + i * 16 + hh * 8 + groupID;
                    sred[warp_n * 128 + rl] = ps[i][hh];
                    sred[256 + warp_n * 128 + rl] = pd[i][hh];
                }
        }
        __syncthreads();
        if (tid < 128) {
            int r = rowBase + tid;
            if (r < M) {
                g_ss[r] = sred[tid] + sred[128 + tid];
                g_sd[r] = sred[256 + tid] + sred[384 + tid];
            }
        }
    }
}

// ---------------- layer1 aggregation (H=128), fused bias+ReLU ---------------
// gathers fp16 h rows (8B per lane per edge), fp32 accumulate
__global__ __launch_bounds__(256) void k_agg1(const float* __restrict__ bias, int N) {
    int warp = (blockIdx.x * blockDim.x + threadIdx.x) >> 5;
    int lane = threadIdx.x & 31;
    if (warp >= N) return;
    int rp = g_rowptr[warp], re = g_rowptr[warp + 1];
    float sd = g_sd[warp];
    float mx = -3.402823466e38f;
    for (int j = rp + lane; j < re; j += 32) {
        float e = g_ss[g_srcidx[j]] + sd;
        e = e > 0.f ? e : 0.2f * e;
        mx = fmaxf(mx, e);
    }
#pragma unroll
    for (int o = 16; o; o >>= 1) mx = fmaxf(mx, __shfl_xor_sync(0xffffffffu, mx, o));

    float4 acc = make_float4(0.f, 0.f, 0.f, 0.f);
    float denom = 0.f;
    int coff = lane << 2;
    int s_cur = (rp < re) ? g_srcidx[rp] : 0;
    float ss_cur = (rp < re) ? g_ss[s_cur] : 0.f;
    uint2 hv_cur = make_uint2(0u, 0u);
    if (rp < re)
        hv_cur = *reinterpret_cast<const uint2*>(&g_hh[(size_t)s_cur * 128 + coff]);
    for (int j = rp; j < re; j++) {
        float ss_nxt = 0.f;
        uint2 hv_nxt = make_uint2(0u, 0u);
        if (j + 1 < re) {
            int s_nxt = g_srcidx[j + 1];
            ss_nxt = g_ss[s_nxt];
            hv_nxt = *reinterpret_cast<const uint2*>(&g_hh[(size_t)s_nxt * 128 + coff]);
        }
        float e = ss_cur + sd;
        e = e > 0.f ? e : 0.2f * e;
        float ex = __expf(e - mx);
        denom += ex;
        float2 f0 = __half22float2(*reinterpret_cast<const __half2*>(&hv_cur.x));
        float2 f1 = __half22float2(*reinterpret_cast<const __half2*>(&hv_cur.y));
        acc.x += ex * f0.x;
        acc.y += ex * f0.y;
        acc.z += ex * f1.x;
        acc.w += ex * f1.y;
        ss_cur = ss_nxt;
        hv_cur = hv_nxt;
    }
    float inv = 1.f / denom;
    float4 o;
    o.x = fmaxf(fmaf(acc.x, inv, bias[coff + 0]), 0.f);
    o.y = fmaxf(fmaf(acc.y, inv, bias[coff + 1]), 0.f);
    o.z = fmaxf(fmaf(acc.z, inv, bias[coff + 2]), 0.f);
    o.w = fmaxf(fmaf(acc.w, inv, bias[coff + 3]), 0.f);
    *reinterpret_cast<float4*>(&g_feat[(size_t)warp * 128 + coff]) = o;
}

// ---------------- layer2 aggregation (C<=64) + fused log_softmax ------------
__global__ __launch_bounds__(256) void k_agg2(const float* __restrict__ bias,
                                              float* __restrict__ out, int N, int C) {
    int warp = (blockIdx.x * blockDim.x + threadIdx.x) >> 5;
    int lane = threadIdx.x & 31;
    if (warp >= N) return;
    int rp = g_rowptr[warp], re = g_rowptr[warp + 1];
    float sd = g_sd[warp];
    float mx = -3.402823466e38f;
    for (int j = rp + lane; j < re; j += 32) {
        float e = g_ss[g_srcidx[j]] + sd;
        e = e > 0.f ? e : 0.2f * e;
        mx = fmaxf(mx, e);
    }
#pragma unroll
    for (int o = 16; o; o >>= 1) mx = fmaxf(mx, __shfl_xor_sync(0xffffffffu, mx, o));

    int c0 = lane, c1 = lane + 32;
    bool v0ok = c0 < C, v1ok = c1 < C;
    float a0 = 0.f, a1 = 0.f, denom = 0.f;
    int s_cur = (rp < re) ? g_srcidx[rp] : 0;
    float ss_cur = (rp < re) ? g_ss[s_cur] : 0.f;
    float h0_cur = 0.f, h1_cur = 0.f;
    if (rp < re) {
        const __half* hr = &g_hh[(size_t)s_cur * C];
        if (v0ok) h0_cur = __half2float(hr[c0]);
        if (v1ok) h1_cur = __half2float(hr[c1]);
    }
    for (int j = rp; j < re; j++) {
        float ss_nxt = 0.f, h0_nxt = 0.f, h1_nxt = 0.f;
        if (j + 1 < re) {
            int s_nxt = g_srcidx[j + 1];
            ss_nxt = g_ss[s_nxt];
            const __half* hr = &g_hh[(size_t)s_nxt * C];
            if (v0ok) h0_nxt = __half2float(hr[c0]);
            if (v1ok) h1_nxt = __half2float(hr[c1]);
        }
        float e = ss_cur + sd;
        e = e > 0.f ? e : 0.2f * e;
        float ex = __expf(e - mx);
        denom += ex;
        a0 += ex * h0_cur;
        a1 += ex * h1_cur;
        ss_cur = ss_nxt;
        h0_cur = h0_nxt;
        h1_cur = h1_nxt;
    }
    float inv = 1.f / denom;
    float v0 = v0ok ? fmaf(a0, inv, bias[c0]) : -3.402823466e38f;
    float v1 = v1ok ? fmaf(a1, inv, bias[c1]) : -3.402823466e38f;
    float m2 = fmaxf(v0, v1);
#pragma unroll
    for (int o = 16; o; o >>= 1) m2 = fmaxf(m2, __shfl_xor_sync(0xffffffffu, m2, o));
    float se = (v0ok ? __expf(v0 - m2) : 0.f) + (v1ok ? __expf(v1 - m2) : 0.f);
#pragma unroll
    for (int o = 16; o; o >>= 1) se += __shfl_xor_sync(0xffffffffu, se, o);
    float lse = m2 + logf(se);
    if (v0ok) out[(size_t)warp * C + c0] = v0 - lse;
    if (v1ok) out[(size_t)warp * C + c1] = v1 - lse;
}

// ---------------- launcher --------------------------------------------------
static inline int cdiv(int a, int b) { return (a + b - 1) / b; }

extern "C" void kernel_launch(void* const* d_in, const int* in_sizes, int n_in,
                              void* d_out, int out_size) {
    const float* x   = (const float*)d_in[0];
    const int* ei32  = (const int*)d_in[1];
    const float* W1  = (const float*)d_in[2];
    const float* as1 = (const float*)d_in[3];
    const float* ad1 = (const float*)d_in[4];
    const float* b1  = (const float*)d_in[5];
    const float* W2  = (const float*)d_in[6];
    const float* as2 = (const float*)d_in[7];
    const float* ad2 = (const float*)d_in[8];
    const float* b2  = (const float*)d_in[9];

    int H = in_sizes[3];
    int C = in_sizes[7];
    int F = in_sizes[2] / H;
    int N = in_sizes[0] / F;
    int E = in_sizes[1] / 2;

    // side stream + fork/join events: created once on first call (outside
    // capture), reused so every captured graph is identical.
    static cudaStream_t side = nullptr;
    static cudaEvent_t evFork = nullptr, evJoin = nullptr;
    if (side == nullptr) {
        cudaStreamCreateWithFlags(&side, cudaStreamNonBlocking);
        cudaEventCreateWithFlags(&evFork, cudaEventDisableTiming);
        cudaEventCreateWithFlags(&evJoin, cudaEventDisableTiming);
    }

    // fork: CSR build chain runs on side stream, concurrent with GEMM1
    cudaEventRecord(evFork, 0);
    cudaStreamWaitEvent(side, evFork, 0);

    int nb = cdiv(N, SCAN_CHUNK);
    k_initdeg<<<cdiv(N, 256), 256, 0, side>>>(ei32, N);
    k_count<<<cdiv(E, 256), 256, 0, side>>>(ei32, E);
    k_scan_blocksum<<<nb, 256, 0, side>>>(N);
    k_scan_partials<<<1, 32, 0, side>>>(nb, N);
    k_scan_blockscan<<<nb, 256, 0, side>>>(N);
    k_fill<<<cdiv(E + N, 256), 256, 0, side>>>(ei32, E, N);

    // layer 1 GEMM (+fused scores) on main stream, overlapped with CSR build
    dim3 g1(cdiv(H, 128), cdiv(N, 128));
    const float* s1 = (g1.x == 1) ? as1 : nullptr;
    k_gemm_tf32<<<g1, 256>>>(N, H, F, x, W1, 0, s1, ad1);

    // join: agg1 needs both CSR and GEMM1 results
    cudaEventRecord(evJoin, side);
    cudaStreamWaitEvent(0, evJoin, 0);

    k_agg1<<<cdiv(N, 8), 256>>>(b1, N);

    // layer 2: h2 = g_feat @ W2 -> g_hh (fp16), scores fused; agg2 -> out
    dim3 g2(cdiv(C, 128), cdiv(N, 128));
    const float* s2 = (g2.x == 1) ? as2 : nullptr;
    k_gemm_tf32<<<g2, 256>>>(N, C, H, nullptr, W2, 1, s2, ad2);
    k_agg2<<<cdiv(N, 8), 256>>>(b2, (float*)d_out, N, C);
}

// round 14
// speedup vs baseline: 2.3645x; 1.0966x over previous
#include <cuda_runtime.h>
#include <cuda_fp16.h>
#include <math.h>
#include <stdint.h>

// ---------------- static scratch (no runtime allocation allowed) ------------
#define NMAX 100000
#define EMAX 1600000
#define ENMAX (EMAX + NMAX)
#define SCAN_CHUNK 1024
#define SCAN_MAXB ((NMAX + SCAN_CHUNK - 1) / SCAN_CHUNK)   // 98

__device__ __half g_hh[(size_t)NMAX * 128];   // h (fp16) — gather payload
__device__ float g_feat[(size_t)NMAX * 128];  // layer1 output features (fp32, GEMM2 A)
__device__ float g_ss[NMAX];                  // per-node src score
__device__ float g_sd[NMAX];                  // per-node dst score
__device__ int   g_deg[NMAX];
__device__ int   g_rowptr[NMAX + 1];
__device__ int   g_cursor[NMAX];
__device__ int   g_srcidx[ENMAX];
__device__ int   g_is64;                      // edge_index dtype flag
__device__ int   g_part[SCAN_MAXB];
__device__ int   g_partoff[SCAN_MAXB];

__device__ __forceinline__ int load_src(const int* ei32, int E, int i) {
    int v = g_is64 ? ei32[2 * i] : ei32[i];
    return min(max(v, 0), NMAX - 1);
}
__device__ __forceinline__ int load_dst(const int* ei32, int E, int i) {
    int v = g_is64 ? ei32[2 * (E + i)] : ei32[E + i];
    return min(max(v, 0), NMAX - 1);
}

// ---------------- CSR build -------------------------------------------------
__global__ void k_initdeg(const int* __restrict__ ei32, int N) {
    int i = blockIdx.x * blockDim.x + threadIdx.x;
    if (i == 0) {
        int acc = ei32[1] | ei32[3] | ei32[5] | ei32[7] |
                  ei32[9] | ei32[11] | ei32[13] | ei32[15];
        g_is64 = (acc == 0) ? 1 : 0;
    }
    if (i < N) g_deg[i] = 1;  // self loop
}

__global__ void k_count(const int* __restrict__ ei32, int E) {
    int i = blockIdx.x * blockDim.x + threadIdx.x;
    if (i < E) atomicAdd(&g_deg[load_dst(ei32, E, i)], 1);
}

__global__ __launch_bounds__(256) void k_scan_blocksum(int n) {
    __shared__ int sh[256];
    int b = blockIdx.x, tid = threadIdx.x;
    int base = b * SCAN_CHUNK + tid * 4;
    int s = 0;
#pragma unroll
    for (int k = 0; k < 4; k++) {
        int i = base + k;
        if (i < n) s += g_deg[i];
    }
    sh[tid] = s;
    __syncthreads();
#pragma unroll
    for (int off = 128; off; off >>= 1) {
        if (tid < off) sh[tid] += sh[tid + off];
        __syncthreads();
    }
    if (tid == 0) g_part[b] = sh[0];
}

__global__ void k_scan_partials(int nb, int n) {
    if (threadIdx.x == 0) {
        int run = 0;
        for (int b = 0; b < nb; b++) {
            g_partoff[b] = run;
            run += g_part[b];
        }
        g_rowptr[n] = run;
    }
}

__global__ __launch_bounds__(256) void k_scan_blockscan(int n) {
    __shared__ int sh[256];
    int b = blockIdx.x, tid = threadIdx.x;
    int base = b * SCAN_CHUNK + tid * 4;
    int v[4];
    int s = 0;
#pragma unroll
    for (int k = 0; k < 4; k++) {
        int i = base + k;
        v[k] = (i < n) ? g_deg[i] : 0;
        s += v[k];
    }
    sh[tid] = s;
    __syncthreads();
    for (int off = 1; off < 256; off <<= 1) {
        int t = (tid >= off) ? sh[tid - off] : 0;
        __syncthreads();
        sh[tid] += t;
        __syncthreads();
    }
    int run = g_partoff[b] + ((tid == 0) ? 0 : sh[tid - 1]);
#pragma unroll
    for (int k = 0; k < 4; k++) {
        int i = base + k;
        if (i < n) {
            g_rowptr[i] = run;
            g_cursor[i] = run;
            run += v[k];
        }
    }
}

__global__ void k_fill(const int* __restrict__ ei32, int E, int N) {
    int i = blockIdx.x * blockDim.x + threadIdx.x;
    if (i >= E + N) return;
    int s, d;
    if (i < E) {
        s = load_src(ei32, E, i);
        d = load_dst(ei32, E, i);
    } else {
        s = d = i - E;
    }
    int pos = atomicAdd(&g_cursor[d], 1);
    if (pos >= 0 && pos < ENMAX) g_srcidx[pos] = s;
}

// ---------------- TF32 tensor GEMM + fused score epilogue -------------------
__device__ __forceinline__ uint32_t f2tf32(float f) {
    uint32_t u;
    asm("cvt.rna.tf32.f32 %0, %1;" : "=r"(u) : "f"(f));
    return u;
}

__device__ __forceinline__ void mma_tf32(float* c, uint32_t a0, uint32_t a1,
                                         uint32_t a2, uint32_t a3,
                                         uint32_t b0, uint32_t b1) {
    asm volatile(
        "mma.sync.aligned.m16n8k8.row.col.f32.tf32.tf32.f32 "
        "{%0,%1,%2,%3}, {%4,%5,%6,%7}, {%8,%9}, {%0,%1,%2,%3};"
        : "+f"(c[0]), "+f"(c[1]), "+f"(c[2]), "+f"(c[3])
        : "r"(a0), "r"(a1), "r"(a2), "r"(a3), "r"(b0), "r"(b1));
}

#define APAD 36
#define BPAD 136

__global__ __launch_bounds__(256, 2) void k_gemm_tf32(
    int M, int Nn, int K,
    const float* __restrict__ Aext, const float* __restrict__ B, int a_sel,
    const float* __restrict__ asrc, const float* __restrict__ adst) {
    const float* A = (a_sel == 0) ? Aext : (const float*)g_feat;

    __shared__ uint32_t As[128][APAD];
    __shared__ uint32_t Bs[32][BPAD];

    int tid = threadIdx.x;
    int lane = tid & 31, wid = tid >> 5;
    int warp_m = wid & 3, warp_n = wid >> 2;
    int groupID = lane >> 2;
    int tig = lane & 3;
    int rowBase = blockIdx.y * 128;
    int colBase = blockIdx.x * 128;

    float acc[2][8][4];
#pragma unroll
    for (int i = 0; i < 2; i++)
#pragma unroll
        for (int j = 0; j < 8; j++)
#pragma unroll
            for (int q = 0; q < 4; q++) acc[i][j][q] = 0.f;

    int aRow = tid >> 1;
    int aSeg = (tid & 1) << 4;
    int bRow = tid >> 3;
    int bSeg = (tid & 7) << 4;
    int gr = rowBase + aRow;
    bool aOk = gr < M;

    float4 av[4], bv[4];
    {
        const float* ap = A + (size_t)gr * K + aSeg;
#pragma unroll
        for (int v = 0; v < 4; v++)
            av[v] = aOk ? *reinterpret_cast<const float4*>(ap + v * 4)
                        : make_float4(0.f, 0.f, 0.f, 0.f);
        const float* bp = B + (size_t)bRow * Nn + colBase + bSeg;
#pragma unroll
        for (int v = 0; v < 4; v++) {
            int c = colBase + bSeg + v * 4;
            float4 f = make_float4(0.f, 0.f, 0.f, 0.f);
            if (c + 3 < Nn) f = *reinterpret_cast<const float4*>(bp + v * 4);
            else if (c < Nn) {
                f.x = bp[v * 4];
                if (c + 1 < Nn) f.y = bp[v * 4 + 1];
                if (c + 2 < Nn) f.z = bp[v * 4 + 2];
            }
            bv[v] = f;
        }
    }
#pragma unroll
    for (int v = 0; v < 4; v++) {
        As[aRow][aSeg + v * 4 + 0] = f2tf32(av[v].x);
        As[aRow][aSeg + v * 4 + 1] = f2tf32(av[v].y);
        As[aRow][aSeg + v * 4 + 2] = f2tf32(av[v].z);
        As[aRow][aSeg + v * 4 + 3] = f2tf32(av[v].w);
        Bs[bRow][bSeg + v * 4 + 0] = f2tf32(bv[v].x);
        Bs[bRow][bSeg + v * 4 + 1] = f2tf32(bv[v].y);
        Bs[bRow][bSeg + v * 4 + 2] = f2tf32(bv[v].z);
        Bs[bRow][bSeg + v * 4 + 3] = f2tf32(bv[v].w);
    }
    __syncthreads();

    for (int kk = 32; kk <= K; kk += 32) {
        bool more = kk < K;
        if (more) {
            const float* ap = A + (size_t)gr * K + kk + aSeg;
#pragma unroll
            for (int v = 0; v < 4; v++)
                av[v] = aOk ? *reinterpret_cast<const float4*>(ap + v * 4)
                            : make_float4(0.f, 0.f, 0.f, 0.f);
            const float* bp = B + (size_t)(kk + bRow) * Nn + colBase + bSeg;
#pragma unroll
            for (int v = 0; v < 4; v++) {
                int c = colBase + bSeg + v * 4;
                float4 f = make_float4(0.f, 0.f, 0.f, 0.f);
                if (c + 3 < Nn) f = *reinterpret_cast<const float4*>(bp + v * 4);
                else if (c < Nn) {
                    f.x = bp[v * 4];
                    if (c + 1 < Nn) f.y = bp[v * 4 + 1];
                    if (c + 2 < Nn) f.z = bp[v * 4 + 2];
                }
                bv[v] = f;
            }
        }
#pragma unroll
        for (int kt = 0; kt < 4; kt++) {
            int k = kt * 8;
            uint32_t b0[8], b1[8];
#pragma unroll
            for (int j = 0; j < 8; j++) {
                int n = warp_n * 64 + j * 8 + groupID;
                b0[j] = Bs[k + tig][n];
                b1[j] = Bs[k + tig + 4][n];
            }
#pragma unroll
            for (int i = 0; i < 2; i++) {
                int m = warp_m * 32 + i * 16;
                uint32_t a0 = As[m + groupID][k + tig];
                uint32_t a1 = As[m + 8 + groupID][k + tig];
                uint32_t a2 = As[m + groupID][k + 4 + tig];
                uint32_t a3 = As[m + 8 + groupID][k + 4 + tig];
#pragma unroll
                for (int j = 0; j < 8; j++)
                    mma_tf32(acc[i][j], a0, a1, a2, a3, b0[j], b1[j]);
            }
        }
        __syncthreads();
        if (more) {
#pragma unroll
            for (int v = 0; v < 4; v++) {
                As[aRow][aSeg + v * 4 + 0] = f2tf32(av[v].x);
                As[aRow][aSeg + v * 4 + 1] = f2tf32(av[v].y);
                As[aRow][aSeg + v * 4 + 2] = f2tf32(av[v].z);
                As[aRow][aSeg + v * 4 + 3] = f2tf32(av[v].w);
                Bs[bRow][bSeg + v * 4 + 0] = f2tf32(bv[v].x);
                Bs[bRow][bSeg + v * 4 + 1] = f2tf32(bv[v].y);
                Bs[bRow][bSeg + v * 4 + 2] = f2tf32(bv[v].z);
                Bs[bRow][bSeg + v * 4 + 3] = f2tf32(bv[v].w);
            }
            __syncthreads();
        }
    }

    // ---- epilogue: write h as fp16 (half2 stores) ----
#pragma unroll
    for (int i = 0; i < 2; i++) {
        int r0 = rowBase + warp_m * 32 + i * 16 + groupID;
        int r1 = r0 + 8;
#pragma unroll
        for (int j = 0; j < 8; j++) {
            int c = colBase + warp_n * 64 + j * 8 + tig * 2;
            if (c + 1 < Nn) {
                if (r0 < M)
                    *reinterpret_cast<__half2*>(&g_hh[(size_t)r0 * Nn + c]) =
                        __floats2half2_rn(acc[i][j][0], acc[i][j][1]);
                if (r1 < M)
                    *reinterpret_cast<__half2*>(&g_hh[(size_t)r1 * Nn + c]) =
                        __floats2half2_rn(acc[i][j][2], acc[i][j][3]);
            } else if (c < Nn) {
                if (r0 < M) g_hh[(size_t)r0 * Nn + c] = __float2half_rn(acc[i][j][0]);
                if (r1 < M) g_hh[(size_t)r1 * Nn + c] = __float2half_rn(acc[i][j][2]);
            }
        }
    }

    // ---- fused scores (fp32, from accumulators; requires gridDim.x==1) ----
    if (asrc != nullptr) {
        float ps[2][2] = {{0.f, 0.f}, {0.f, 0.f}};
        float pd[2][2] = {{0.f, 0.f}, {0.f, 0.f}};
#pragma unroll
        for (int j = 0; j < 8; j++) {
            int c = warp_n * 64 + j * 8 + tig * 2;
            float a0 = (c < Nn) ? asrc[c] : 0.f;
            float a1 = (c + 1 < Nn) ? asrc[c + 1] : 0.f;
            float d0 = (c < Nn) ? adst[c] : 0.f;
            float d1 = (c + 1 < Nn) ? adst[c + 1] : 0.f;
#pragma unroll
            for (int i = 0; i < 2; i++) {
                ps[i][0] += acc[i][j][0] * a0 + acc[i][j][1] * a1;
                ps[i][1] += acc[i][j][2] * a0 + acc[i][j][3] * a1;
                pd[i][0] += acc[i][j][0] * d0 + acc[i][j][1] * d1;
                pd[i][1] += acc[i][j][2] * d0 + acc[i][j][3] * d1;
            }
        }
#pragma unroll
        for (int off = 1; off <= 2; off <<= 1) {
#pragma unroll
            for (int i = 0; i < 2; i++)
#pragma unroll
                for (int hh = 0; hh < 2; hh++) {
                    ps[i][hh] += __shfl_xor_sync(0xffffffffu, ps[i][hh], off);
                    pd[i][hh] += __shfl_xor_sync(0xffffffffu, pd[i][hh], off);
                }
        }
        float* sred = reinterpret_cast<float*>(&As[0][0]);
        __syncthreads();
        if (tig == 0) {
#pragma unroll
            for (int i = 0; i < 2; i++)
#pragma unroll
                for (int hh = 0; hh < 2; hh++) {
                    int rl = warp_m * 32 + i * 16 + hh * 8 + groupID;
                    sred[warp_n * 128 + rl] = ps[i][hh];
                    sred[256 + warp_n * 128 + rl] = pd[i][hh];
                }
        }
        __syncthreads();
        if (tid < 128) {
            int r = rowBase + tid;
            if (r < M) {
                g_ss[r] = sred[tid] + sred[128 + tid];
                g_sd[r] = sred[256 + tid] + sred[384 + tid];
            }
        }
    }
}

// ---------------- layer1 aggregation: register-stashed edges, MLP-4 gather --
#define NEG_INF (-3.402823466e38f)

__global__ __launch_bounds__(256) void k_agg1(const float* __restrict__ bias, int N) {
    int warp = (blockIdx.x * blockDim.x + threadIdx.x) >> 5;
    int lane = threadIdx.x & 31;
    if (warp >= N) return;
    int rp = g_rowptr[warp], re = g_rowptr[warp + 1];
    int deg = re - rp;
    float sd = g_sd[warp];

    // pass 1: stash src + leaky(e) for up to 96 edges, lane-parallel
    int s_reg[3];
    float e_reg[3];
    float mx = NEG_INF;
#pragma unroll
    for (int t = 0; t < 3; t++) {
        int j = rp + t * 32 + lane;
        bool ok = j < re;
        int s = ok ? g_srcidx[j] : 0;
        s_reg[t] = s;
        float e = ok ? (g_ss[s] + sd) : NEG_INF;
        if (ok) e = e > 0.f ? e : 0.2f * e;
        e_reg[t] = e;
        mx = fmaxf(mx, e);
    }
    // overflow (deg > 96): rare slow path contributes to max too
    for (int j = rp + 96 + lane; j < re; j += 32) {
        float e = g_ss[g_srcidx[j]] + sd;
        e = e > 0.f ? e : 0.2f * e;
        mx = fmaxf(mx, e);
    }
#pragma unroll
    for (int o = 16; o; o >>= 1) mx = fmaxf(mx, __shfl_xor_sync(0xffffffffu, mx, o));

    // exps lane-parallel; denom reduced across warp
    float ex_reg[3];
    float dsum = 0.f;
#pragma unroll
    for (int t = 0; t < 3; t++) {
        float ex = (e_reg[t] > NEG_INF) ? __expf(e_reg[t] - mx) : 0.f;
        ex_reg[t] = ex;
        dsum += ex;
    }
#pragma unroll
    for (int o = 16; o; o >>= 1) dsum += __shfl_xor_sync(0xffffffffu, dsum, o);
    float denom = dsum;

    // pass 2: gather h rows; s/ex via shfl (no memory), loads 4-deep
    float4 acc = make_float4(0.f, 0.f, 0.f, 0.f);
    int coff = lane << 2;
    int jmax = min(deg, 96);
#pragma unroll
    for (int t = 0; t < 3; t++) {
        int base = t * 32;
        if (base >= jmax) break;
        int cnt = min(32, jmax - base);
        int jl = 0;
        for (; jl + 4 <= cnt; jl += 4) {
            int s0 = __shfl_sync(0xffffffffu, s_reg[t], jl + 0);
            int s1 = __shfl_sync(0xffffffffu, s_reg[t], jl + 1);
            int s2 = __shfl_sync(0xffffffffu, s_reg[t], jl + 2);
            int s3 = __shfl_sync(0xffffffffu, s_reg[t], jl + 3);
            uint2 h0 = *reinterpret_cast<const uint2*>(&g_hh[(size_t)s0 * 128 + coff]);
            uint2 h1 = *reinterpret_cast<const uint2*>(&g_hh[(size_t)s1 * 128 + coff]);
            uint2 h2 = *reinterpret_cast<const uint2*>(&g_hh[(size_t)s2 * 128 + coff]);
            uint2 h3 = *reinterpret_cast<const uint2*>(&g_hh[(size_t)s3 * 128 + coff]);
            float ex0 = __shfl_sync(0xffffffffu, ex_reg[t], jl + 0);
            float ex1 = __shfl_sync(0xffffffffu, ex_reg[t], jl + 1);
            float ex2 = __shfl_sync(0xffffffffu, ex_reg[t], jl + 2);
            float ex3 = __shfl_sync(0xffffffffu, ex_reg[t], jl + 3);
            float2 a0 = __half22float2(*reinterpret_cast<const __half2*>(&h0.x));
            float2 b0 = __half22float2(*reinterpret_cast<const __half2*>(&h0.y));
            float2 a1 = __half22float2(*reinterpret_cast<const __half2*>(&h1.x));
            float2 b1 = __half22float2(*reinterpret_cast<const __half2*>(&h1.y));
            float2 a2 = __half22float2(*reinterpret_cast<const __half2*>(&h2.x));
            float2 b2 = __half22float2(*reinterpret_cast<const __half2*>(&h2.y));
            float2 a3 = __half22float2(*reinterpret_cast<const __half2*>(&h3.x));
            float2 b3 = __half22float2(*reinterpret_cast<const __half2*>(&h3.y));
            acc.x += ex0 * a0.x + ex1 * a1.x + ex2 * a2.x + ex3 * a3.x;
            acc.y += ex0 * a0.y + ex1 * a1.y + ex2 * a2.y + ex3 * a3.y;
            acc.z += ex0 * b0.x + ex1 * b1.x + ex2 * b2.x + ex3 * b3.x;
            acc.w += ex0 * b0.y + ex1 * b1.y + ex2 * b2.y + ex3 * b3.y;
        }
        for (; jl < cnt; jl++) {
            int s0 = __shfl_sync(0xffffffffu, s_reg[t], jl);
            float ex0 = __shfl_sync(0xffffffffu, ex_reg[t], jl);
            uint2 h0 = *reinterpret_cast<const uint2*>(&g_hh[(size_t)s0 * 128 + coff]);
            float2 a0 = __half22float2(*reinterpret_cast<const __half2*>(&h0.x));
            float2 b0 = __half22float2(*reinterpret_cast<const __half2*>(&h0.y));
            acc.x += ex0 * a0.x;
            acc.y += ex0 * a0.y;
            acc.z += ex0 * b0.x;
            acc.w += ex0 * b0.y;
        }
    }
    // overflow slow path (deg > 96): broadcast loads, add to denom first
    if (deg > 96) {
        for (int j = rp + 96; j < re; j++) {
            int s = g_srcidx[j];
            float e = g_ss[s] + sd;
            e = e > 0.f ? e : 0.2f * e;
            float ex = __expf(e - mx);
            denom += ex;
            uint2 h0 = *reinterpret_cast<const uint2*>(&g_hh[(size_t)s * 128 + coff]);
            float2 a0 = __half22float2(*reinterpret_cast<const __half2*>(&h0.x));
            float2 b0 = __half22float2(*reinterpret_cast<const __half2*>(&h0.y));
            acc.x += ex * a0.x;
            acc.y += ex * a0.y;
            acc.z += ex * b0.x;
            acc.w += ex * b0.y;
        }
    }

    float inv = 1.f / denom;
    float4 o;
    o.x = fmaxf(fmaf(acc.x, inv, bias[coff + 0]), 0.f);
    o.y = fmaxf(fmaf(acc.y, inv, bias[coff + 1]), 0.f);
    o.z = fmaxf(fmaf(acc.z, inv, bias[coff + 2]), 0.f);
    o.w = fmaxf(fmaf(acc.w, inv, bias[coff + 3]), 0.f);
    *reinterpret_cast<float4*>(&g_feat[(size_t)warp * 128 + coff]) = o;
}

// ---------------- layer2 aggregation (C<=64) + fused log_softmax ------------
__global__ __launch_bounds__(256) void k_agg2(const float* __restrict__ bias,
                                              float* __restrict__ out, int N, int C) {
    int warp = (blockIdx.x * blockDim.x + threadIdx.x) >> 5;
    int lane = threadIdx.x & 31;
    if (warp >= N) return;
    int rp = g_rowptr[warp], re = g_rowptr[warp + 1];
    int deg = re - rp;
    float sd = g_sd[warp];

    int s_reg[3];
    float e_reg[3];
    float mx = NEG_INF;
#pragma unroll
    for (int t = 0; t < 3; t++) {
        int j = rp + t * 32 + lane;
        bool ok = j < re;
        int s = ok ? g_srcidx[j] : 0;
        s_reg[t] = s;
        float e = ok ? (g_ss[s] + sd) : NEG_INF;
        if (ok) e = e > 0.f ? e : 0.2f * e;
        e_reg[t] = e;
        mx = fmaxf(mx, e);
    }
    for (int j = rp + 96 + lane; j < re; j += 32) {
        float e = g_ss[g_srcidx[j]] + sd;
        e = e > 0.f ? e : 0.2f * e;
        mx = fmaxf(mx, e);
    }
#pragma unroll
    for (int o = 16; o; o >>= 1) mx = fmaxf(mx, __shfl_xor_sync(0xffffffffu, mx, o));

    float ex_reg[3];
    float dsum = 0.f;
#pragma unroll
    for (int t = 0; t < 3; t++) {
        float ex = (e_reg[t] > NEG_INF) ? __expf(e_reg[t] - mx) : 0.f;
        ex_reg[t] = ex;
        dsum += ex;
    }
#pragma unroll
    for (int o = 16; o; o >>= 1) dsum += __shfl_xor_sync(0xffffffffu, dsum, o);
    float denom = dsum;

    int c0 = lane, c1 = lane + 32;
    bool v0ok = c0 < C, v1ok = c1 < C;
    float a0 = 0.f, a1 = 0.f;
    int jmax = min(deg, 96);
#pragma unroll
    for (int t = 0; t < 3; t++) {
        int base = t * 32;
        if (base >= jmax) break;
        int cnt = min(32, jmax - base);
        int jl = 0;
        for (; jl + 4 <= cnt; jl += 4) {
            int s0 = __shfl_sync(0xffffffffu, s_reg[t], jl + 0);
            int s1 = __shfl_sync(0xffffffffu, s_reg[t], jl + 1);
            int s2 = __shfl_sync(0xffffffffu, s_reg[t], jl + 2);
            int s3 = __shfl_sync(0xffffffffu, s_reg[t], jl + 3);
            float h00 = v0ok ? __half2float(g_hh[(size_t)s0 * C + c0]) : 0.f;
            float h10 = v0ok ? __half2float(g_hh[(size_t)s1 * C + c0]) : 0.f;
            float h20 = v0ok ? __half2float(g_hh[(size_t)s2 * C + c0]) : 0.f;
            float h30 = v0ok ? __half2float(g_hh[(size_t)s3 * C + c0]) : 0.f;
            float h01 = v1ok ? __half2float(g_hh[(size_t)s0 * C + c1]) : 0.f;
            float h11 = v1ok ? __half2float(g_hh[(size_t)s1 * C + c1]) : 0.f;
            float h21 = v1ok ? __half2float(g_hh[(size_t)s2 * C + c1]) : 0.f;
            float h31 = v1ok ? __half2float(g_hh[(size_t)s3 * C + c1]) : 0.f;
            float ex0 = __shfl_sync(0xffffffffu, ex_reg[t], jl + 0);
            float ex1 = __shfl_sync(0xffffffffu, ex_reg[t], jl + 1);
            float ex2 = __shfl_sync(0xffffffffu, ex_reg[t], jl + 2);
            float ex3 = __shfl_sync(0xffffffffu, ex_reg[t], jl + 3);
            a0 += ex0 * h00 + ex1 * h10 + ex2 * h20 + ex3 * h30;
            a1 += ex0 * h01 + ex1 * h11 + ex2 * h21 + ex3 * h31;
        }
        for (; jl < cnt; jl++) {
            int s0 = __shfl_sync(0xffffffffu, s_reg[t], jl);
            float ex0 = __shfl_sync(0xffffffffu, ex_reg[t], jl);
            float h00 = v0ok ? __half2float(g_hh[(size_t)s0 * C + c0]) : 0.f;
            float h01 = v1ok ? __half2float(g_hh[(size_t)s0 * C + c1]) : 0.f;
            a0 += ex0 * h00;
            a1 += ex0 * h01;
        }
    }
    if (deg > 96) {
        for (int j = rp + 96; j < re; j++) {
            int s = g_srcidx[j];
            float e = g_ss[s] + sd;
            e = e > 0.f ? e : 0.2f * e;
            float ex = __expf(e - mx);
            denom += ex;
            float h00 = v0ok ? __half2float(g_hh[(size_t)s * C + c0]) : 0.f;
            float h01 = v1ok ? __half2float(g_hh[(size_t)s * C + c1]) : 0.f;
            a0 += ex * h00;
            a1 += ex * h01;
        }
    }

    float inv = 1.f / denom;
    float v0 = v0ok ? fmaf(a0, inv, bias[c0]) : NEG_INF;
    float v1 = v1ok ? fmaf(a1, inv, bias[c1]) : NEG_INF;
    float m2 = fmaxf(v0, v1);
#pragma unroll
    for (int o = 16; o; o >>= 1) m2 = fmaxf(m2, __shfl_xor_sync(0xffffffffu, m2, o));
    float se = (v0ok ? __expf(v0 - m2) : 0.f) + (v1ok ? __expf(v1 - m2) : 0.f);
#pragma unroll
    for (int o = 16; o; o >>= 1) se += __shfl_xor_sync(0xffffffffu, se, o);
    float lse = m2 + logf(se);
    if (v0ok) out[(size_t)warp * C + c0] = v0 - lse;
    if (v1ok) out[(size_t)warp * C + c1] = v1 - lse;
}

// ---------------- launcher --------------------------------------------------
static inline int cdiv(int a, int b) { return (a + b - 1) / b; }

extern "C" void kernel_launch(void* const* d_in, const int* in_sizes, int n_in,
                              void* d_out, int out_size) {
    const float* x   = (const float*)d_in[0];
    const int* ei32  = (const int*)d_in[1];
    const float* W1  = (const float*)d_in[2];
    const float* as1 = (const float*)d_in[3];
    const float* ad1 = (const float*)d_in[4];
    const float* b1  = (const float*)d_in[5];
    const float* W2  = (const float*)d_in[6];
    const float* as2 = (const float*)d_in[7];
    const float* ad2 = (const float*)d_in[8];
    const float* b2  = (const float*)d_in[9];

    int H = in_sizes[3];
    int C = in_sizes[7];
    int F = in_sizes[2] / H;
    int N = in_sizes[0] / F;
    int E = in_sizes[1] / 2;

    static cudaStream_t side = nullptr;
    static cudaEvent_t evFork = nullptr, evJoin = nullptr;
    if (side == nullptr) {
        cudaStreamCreateWithFlags(&side, cudaStreamNonBlocking);
        cudaEventCreateWithFlags(&evFork, cudaEventDisableTiming);
        cudaEventCreateWithFlags(&evJoin, cudaEventDisableTiming);
    }

    cudaEventRecord(evFork, 0);
    cudaStreamWaitEvent(side, evFork, 0);

    int nb = cdiv(N, SCAN_CHUNK);
    k_initdeg<<<cdiv(N, 256), 256, 0, side>>>(ei32, N);
    k_count<<<cdiv(E, 256), 256, 0, side>>>(ei32, E);
    k_scan_blocksum<<<nb, 256, 0, side>>>(N);
    k_scan_partials<<<1, 32, 0, side>>>(nb, N);
    k_scan_blockscan<<<nb, 256, 0, side>>>(N);
    k_fill<<<cdiv(E + N, 256), 256, 0, side>>>(ei32, E, N);

    dim3 g1(cdiv(H, 128), cdiv(N, 128));
    const float* s1 = (g1.x == 1) ? as1 : nullptr;
    k_gemm_tf32<<<g1, 256>>>(N, H, F, x, W1, 0, s1, ad1);

    cudaEventRecord(evJoin, side);
    cudaStreamWaitEvent(0, evJoin, 0);

    k_agg1<<<cdiv(N, 8), 256>>>(b1, N);

    dim3 g2(cdiv(C, 128), cdiv(N, 128));
    const float* s2 = (g2.x == 1) ? as2 : nullptr;
    k_gemm_tf32<<<g2, 256>>>(N, C, H, nullptr, W2, 1, s2, ad2);
    k_agg2<<<cdiv(N, 8), 256>>>(b2, (float*)d_out, N, C);
}

// round 15
// speedup vs baseline: 2.4718x; 1.0454x over previous
#include <cuda_runtime.h>
#include <cuda_fp16.h>
#include <math.h>
#include <stdint.h>

// ---------------- static scratch (no runtime allocation allowed) ------------
#define NMAX 100000
#define EMAX 1600000
#define ENMAX (EMAX + NMAX)
#define SCAN_CHUNK 1024
#define SCAN_MAXB ((NMAX + SCAN_CHUNK - 1) / SCAN_CHUNK)   // 98

__device__ __half g_hh[(size_t)NMAX * 128];   // h (fp16) — gather payload
__device__ float g_feat[(size_t)NMAX * 128];  // layer1 output features (fp32, GEMM2 A)
__device__ float g_ss[NMAX];                  // per-node src score
__device__ float g_sd[NMAX];                  // per-node dst score
__device__ int   g_deg[NMAX];
__device__ int   g_rowptr[NMAX + 1];
__device__ int   g_cursor[NMAX];
__device__ int   g_srcidx[ENMAX];
__device__ int   g_is64;                      // edge_index dtype flag
__device__ int   g_part[SCAN_MAXB];
__device__ int   g_partoff[SCAN_MAXB];

__device__ __forceinline__ int load_src(const int* ei32, int E, int i) {
    int v = g_is64 ? ei32[2 * i] : ei32[i];
    return min(max(v, 0), NMAX - 1);
}
__device__ __forceinline__ int load_dst(const int* ei32, int E, int i) {
    int v = g_is64 ? ei32[2 * (E + i)] : ei32[E + i];
    return min(max(v, 0), NMAX - 1);
}

// ---------------- CSR build -------------------------------------------------
__global__ void k_initdeg(const int* __restrict__ ei32, int N) {
    int i = blockIdx.x * blockDim.x + threadIdx.x;
    if (i == 0) {
        int acc = ei32[1] | ei32[3] | ei32[5] | ei32[7] |
                  ei32[9] | ei32[11] | ei32[13] | ei32[15];
        g_is64 = (acc == 0) ? 1 : 0;
    }
    if (i < N) g_deg[i] = 1;  // self loop
}

__global__ void k_count(const int* __restrict__ ei32, int E) {
    int i = blockIdx.x * blockDim.x + threadIdx.x;
    if (i < E) atomicAdd(&g_deg[load_dst(ei32, E, i)], 1);
}

__global__ __launch_bounds__(256) void k_scan_blocksum(int n) {
    __shared__ int sh[256];
    int b = blockIdx.x, tid = threadIdx.x;
    int base = b * SCAN_CHUNK + tid * 4;
    int s = 0;
#pragma unroll
    for (int k = 0; k < 4; k++) {
        int i = base + k;
        if (i < n) s += g_deg[i];
    }
    sh[tid] = s;
    __syncthreads();
#pragma unroll
    for (int off = 128; off; off >>= 1) {
        if (tid < off) sh[tid] += sh[tid + off];
        __syncthreads();
    }
    if (tid == 0) g_part[b] = sh[0];
}

__global__ void k_scan_partials(int nb, int n) {
    if (threadIdx.x == 0) {
        int run = 0;
        for (int b = 0; b < nb; b++) {
            g_partoff[b] = run;
            run += g_part[b];
        }
        g_rowptr[n] = run;
    }
}

__global__ __launch_bounds__(256) void k_scan_blockscan(int n) {
    __shared__ int sh[256];
    int b = blockIdx.x, tid = threadIdx.x;
    int base = b * SCAN_CHUNK + tid * 4;
    int v[4];
    int s = 0;
#pragma unroll
    for (int k = 0; k < 4; k++) {
        int i = base + k;
        v[k] = (i < n) ? g_deg[i] : 0;
        s += v[k];
    }
    sh[tid] = s;
    __syncthreads();
    for (int off = 1; off < 256; off <<= 1) {
        int t = (tid >= off) ? sh[tid - off] : 0;
        __syncthreads();
        sh[tid] += t;
        __syncthreads();
    }
    int run = g_partoff[b] + ((tid == 0) ? 0 : sh[tid - 1]);
#pragma unroll
    for (int k = 0; k < 4; k++) {
        int i = base + k;
        if (i < n) {
            g_rowptr[i] = run;
            g_cursor[i] = run;
            run += v[k];
        }
    }
}

__global__ void k_fill(const int* __restrict__ ei32, int E, int N) {
    int i = blockIdx.x * blockDim.x + threadIdx.x;
    if (i >= E + N) return;
    int s, d;
    if (i < E) {
        s = load_src(ei32, E, i);
        d = load_dst(ei32, E, i);
    } else {
        s = d = i - E;
    }
    int pos = atomicAdd(&g_cursor[d], 1);
    if (pos >= 0 && pos < ENMAX) g_srcidx[pos] = s;
}

// ---------------- BF16 tensor GEMM (m16n8k16) + fused score epilogue --------
// smem: packed bf16x2 words, 20-word row pitch => banks 20g+tg cover all 32.
__device__ __forceinline__ uint32_t f2bf2(float lo, float hi) {
    uint32_t u;
    asm("cvt.rn.bf16x2.f32 %0, %1, %2;" : "=r"(u) : "f"(hi), "f"(lo));
    return u;
}

__device__ __forceinline__ void mma_bf16(float* c, uint32_t a0, uint32_t a1,
                                         uint32_t a2, uint32_t a3,
                                         uint32_t b0, uint32_t b1) {
    asm volatile(
        "mma.sync.aligned.m16n8k16.row.col.f32.bf16.bf16.f32 "
        "{%0,%1,%2,%3}, {%4,%5,%6,%7}, {%8,%9}, {%0,%1,%2,%3};"
        : "+f"(c[0]), "+f"(c[1]), "+f"(c[2]), "+f"(c[3])
        : "r"(a0), "r"(a1), "r"(a2), "r"(a3), "r"(b0), "r"(b1));
}

#define SPITCH 20   // words per row; 20*g + tg mod 32 hits all banks

__global__ __launch_bounds__(256, 2) void k_gemm_bf16(
    int M, int Nn, int K,
    const float* __restrict__ Aext, const float* __restrict__ B, int a_sel,
    const float* __restrict__ asrc, const float* __restrict__ adst) {
    const float* A = (a_sel == 0) ? Aext : (const float*)g_feat;

    __shared__ uint32_t As[128][SPITCH];  // [m][k/2], 16 words used
    __shared__ uint32_t Bs[128][SPITCH];  // [n][k/2], 16 words used

    int tid = threadIdx.x;
    int lane = tid & 31, wid = tid >> 5;
    int warp_m = wid & 3, warp_n = wid >> 2;
    int groupID = lane >> 2;
    int tig = lane & 3;
    int rowBase = blockIdx.y * 128;
    int colBase = blockIdx.x * 128;

    float acc[2][8][4];
#pragma unroll
    for (int i = 0; i < 2; i++)
#pragma unroll
        for (int j = 0; j < 8; j++)
#pragma unroll
            for (int q = 0; q < 4; q++) acc[i][j][q] = 0.f;

    // A staging: 2 threads per row, each 16 consecutive k (4x float4)
    int aRow = tid >> 1;
    int aSeg = (tid & 1) << 4;          // k offset 0 / 16
    int gr = rowBase + aRow;
    bool aOk = gr < M;
    // B staging (transpose): 2 tasks/thread; q = k-pair, nb = 4-col group
    float4 av[4];
    float4 blo[2], bhi[2];              // per task: rows 2q, 2q+1 (4 cols)

    // helper lambda-ish macro via code dup: load a K-tile into regs
#define LOAD_TILE(kkOff)                                                      \
    {                                                                         \
        const float* ap = A + (size_t)gr * K + (kkOff) + aSeg;                \
        _Pragma("unroll")                                                     \
        for (int v = 0; v < 4; v++)                                           \
            av[v] = aOk ? *reinterpret_cast<const float4*>(ap + v * 4)        \
                        : make_float4(0.f, 0.f, 0.f, 0.f);                    \
        _Pragma("unroll")                                                     \
        for (int rep = 0; rep < 2; rep++) {                                   \
            int task = tid + rep * 256;                                       \
            int q = task & 15;                                                \
            int nb = (task >> 4) << 2;                                        \
            int c = colBase + nb;                                             \
            const float* b0p = B + (size_t)((kkOff) + 2 * q) * Nn + c;        \
            const float* b1p = B + (size_t)((kkOff) + 2 * q + 1) * Nn + c;    \
            float4 lo = make_float4(0.f, 0.f, 0.f, 0.f);                      \
            float4 hi = make_float4(0.f, 0.f, 0.f, 0.f);                      \
            if (c + 3 < Nn) {                                                 \
                lo = *reinterpret_cast<const float4*>(b0p);                   \
                hi = *reinterpret_cast<const float4*>(b1p);                   \
            } else if (c < Nn) {                                              \
                lo.x = b0p[0]; hi.x = b1p[0];                                 \
                if (c + 1 < Nn) { lo.y = b0p[1]; hi.y = b1p[1]; }             \
                if (c + 2 < Nn) { lo.z = b0p[2]; hi.z = b1p[2]; }             \
            }                                                                 \
            blo[rep] = lo; bhi[rep] = hi;                                     \
        }                                                                     \
    }

#define STORE_TILE()                                                          \
    {                                                                         \
        int wbase = aSeg >> 1;                                                \
        As[aRow][wbase + 0] = f2bf2(av[0].x, av[0].y);                        \
        As[aRow][wbase + 1] = f2bf2(av[0].z, av[0].w);                        \
        As[aRow][wbase + 2] = f2bf2(av[1].x, av[1].y);                        \
        As[aRow][wbase + 3] = f2bf2(av[1].z, av[1].w);                        \
        As[aRow][wbase + 4] = f2bf2(av[2].x, av[2].y);                        \
        As[aRow][wbase + 5] = f2bf2(av[2].z, av[2].w);                        \
        As[aRow][wbase + 6] = f2bf2(av[3].x, av[3].y);                        \
        As[aRow][wbase + 7] = f2bf2(av[3].z, av[3].w);                        \
        _Pragma("unroll")                                                     \
        for (int rep = 0; rep < 2; rep++) {                                   \
            int task = tid + rep * 256;                                       \
            int q = task & 15;                                                \
            int nb = (task >> 4) << 2;                                        \
            Bs[nb + 0][q] = f2bf2(blo[rep].x, bhi[rep].x);                    \
            Bs[nb + 1][q] = f2bf2(blo[rep].y, bhi[rep].y);                    \
            Bs[nb + 2][q] = f2bf2(blo[rep].z, bhi[rep].z);                    \
            Bs[nb + 3][q] = f2bf2(blo[rep].w, bhi[rep].w);                    \
        }                                                                     \
    }

    LOAD_TILE(0);
    STORE_TILE();
    __syncthreads();

    for (int kk = 32; kk <= K; kk += 32) {
        bool more = kk < K;
        if (more) LOAD_TILE(kk);
        // compute current tile: 2 k16 steps
#pragma unroll
        for (int kt = 0; kt < 2; kt++) {
            int w = kt * 8 + tig;
            uint32_t b0[8], b1[8];
#pragma unroll
            for (int j = 0; j < 8; j++) {
                int n = warp_n * 64 + j * 8 + groupID;
                b0[j] = Bs[n][w];
                b1[j] = Bs[n][w + 4];
            }
#pragma unroll
            for (int i = 0; i < 2; i++) {
                int m = warp_m * 32 + i * 16;
                uint32_t a0 = As[m + groupID][w];
                uint32_t a1 = As[m + 8 + groupID][w];
                uint32_t a2 = As[m + groupID][w + 4];
                uint32_t a3 = As[m + 8 + groupID][w + 4];
#pragma unroll
                for (int j = 0; j < 8; j++)
                    mma_bf16(acc[i][j], a0, a1, a2, a3, b0[j], b1[j]);
            }
        }
        __syncthreads();
        if (more) {
            STORE_TILE();
            __syncthreads();
        }
    }

    // ---- epilogue: write h as fp16 (half2 stores) ----
#pragma unroll
    for (int i = 0; i < 2; i++) {
        int r0 = rowBase + warp_m * 32 + i * 16 + groupID;
        int r1 = r0 + 8;
#pragma unroll
        for (int j = 0; j < 8; j++) {
            int c = colBase + warp_n * 64 + j * 8 + tig * 2;
            if (c + 1 < Nn) {
                if (r0 < M)
                    *reinterpret_cast<__half2*>(&g_hh[(size_t)r0 * Nn + c]) =
                        __floats2half2_rn(acc[i][j][0], acc[i][j][1]);
                if (r1 < M)
                    *reinterpret_cast<__half2*>(&g_hh[(size_t)r1 * Nn + c]) =
                        __floats2half2_rn(acc[i][j][2], acc[i][j][3]);
            } else if (c < Nn) {
                if (r0 < M) g_hh[(size_t)r0 * Nn + c] = __float2half_rn(acc[i][j][0]);
                if (r1 < M) g_hh[(size_t)r1 * Nn + c] = __float2half_rn(acc[i][j][2]);
            }
        }
    }

    // ---- fused scores (fp32, from accumulators; requires gridDim.x==1) ----
    if (asrc != nullptr) {
        float ps[2][2] = {{0.f, 0.f}, {0.f, 0.f}};
        float pd[2][2] = {{0.f, 0.f}, {0.f, 0.f}};
#pragma unroll
        for (int j = 0; j < 8; j++) {
            int c = warp_n * 64 + j * 8 + tig * 2;
            float a0 = (c < Nn) ? asrc[c] : 0.f;
            float a1 = (c + 1 < Nn) ? asrc[c + 1] : 0.f;
            float d0 = (c < Nn) ? adst[c] : 0.f;
            float d1 = (c + 1 < Nn) ? adst[c + 1] : 0.f;
#pragma unroll
            for (int i = 0; i < 2; i++) {
                ps[i][0] += acc[i][j][0] * a0 + acc[i][j][1] * a1;
                ps[i][1] += acc[i][j][2] * a0 + acc[i][j][3] * a1;
                pd[i][0] += acc[i][j][0] * d0 + acc[i][j][1] * d1;
                pd[i][1] += acc[i][j][2] * d0 + acc[i][j][3] * d1;
            }
        }
#pragma unroll
        for (int off = 1; off <= 2; off <<= 1) {
#pragma unroll
            for (int i = 0; i < 2; i++)
#pragma unroll
                for (int hh = 0; hh < 2; hh++) {
                    ps[i][hh] += __shfl_xor_sync(0xffffffffu, ps[i][hh], off);
                    pd[i][hh] += __shfl_xor_sync(0xffffffffu, pd[i][hh], off);
                }
        }
        float* sred = reinterpret_cast<float*>(&As[0][0]);
        __syncthreads();
        if (tig == 0) {
#pragma unroll
            for (int i = 0; i < 2; i++)
#pragma unroll
                for (int hh = 0; hh < 2; hh++) {
                    int rl = warp_m * 32 + i * 16 + hh * 8 + groupID;
                    sred[warp_n * 128 + rl] = ps[i][hh];
                    sred[256 + warp_n * 128 + rl] = pd[i][hh];
                }
        }
        __syncthreads();
        if (tid < 128) {
            int r = rowBase + tid;
            if (r < M) {
                g_ss[r] = sred[tid] + sred[128 + tid];
                g_sd[r] = sred[256 + tid] + sred[384 + tid];
            }
        }
    }
}

// ---------------- layer1 aggregation: register-stashed edges, MLP-4 gather --
#define NEG_INF (-3.402823466e38f)

__global__ __launch_bounds__(256) void k_agg1(const float* __restrict__ bias, int N) {
    int warp = (blockIdx.x * blockDim.x + threadIdx.x) >> 5;
    int lane = threadIdx.x & 31;
    if (warp >= N) return;
    int rp = g_rowptr[warp], re = g_rowptr[warp + 1];
    int deg = re - rp;
    float sd = g_sd[warp];

    int s_reg[3];
    float e_reg[3];
    float mx = NEG_INF;
#pragma unroll
    for (int t = 0; t < 3; t++) {
        int j = rp + t * 32 + lane;
        bool ok = j < re;
        int s = ok ? g_srcidx[j] : 0;
        s_reg[t] = s;
        float e = ok ? (g_ss[s] + sd) : NEG_INF;
        if (ok) e = e > 0.f ? e : 0.2f * e;
        e_reg[t] = e;
        mx = fmaxf(mx, e);
    }
    for (int j = rp + 96 + lane; j < re; j += 32) {
        float e = g_ss[g_srcidx[j]] + sd;
        e = e > 0.f ? e : 0.2f * e;
        mx = fmaxf(mx, e);
    }
#pragma unroll
    for (int o = 16; o; o >>= 1) mx = fmaxf(mx, __shfl_xor_sync(0xffffffffu, mx, o));

    float ex_reg[3];
    float dsum = 0.f;
#pragma unroll
    for (int t = 0; t < 3; t++) {
        float ex = (e_reg[t] > NEG_INF) ? __expf(e_reg[t] - mx) : 0.f;
        ex_reg[t] = ex;
        dsum += ex;
    }
#pragma unroll
    for (int o = 16; o; o >>= 1) dsum += __shfl_xor_sync(0xffffffffu, dsum, o);
    float denom = dsum;

    float4 acc = make_float4(0.f, 0.f, 0.f, 0.f);
    int coff = lane << 2;
    int jmax = min(deg, 96);
#pragma unroll
    for (int t = 0; t < 3; t++) {
        int base = t * 32;
        if (base >= jmax) break;
        int cnt = min(32, jmax - base);
        int jl = 0;
        for (; jl + 4 <= cnt; jl += 4) {
            int s0 = __shfl_sync(0xffffffffu, s_reg[t], jl + 0);
            int s1 = __shfl_sync(0xffffffffu, s_reg[t], jl + 1);
            int s2 = __shfl_sync(0xffffffffu, s_reg[t], jl + 2);
            int s3 = __shfl_sync(0xffffffffu, s_reg[t], jl + 3);
            uint2 h0 = *reinterpret_cast<const uint2*>(&g_hh[(size_t)s0 * 128 + coff]);
            uint2 h1 = *reinterpret_cast<const uint2*>(&g_hh[(size_t)s1 * 128 + coff]);
            uint2 h2 = *reinterpret_cast<const uint2*>(&g_hh[(size_t)s2 * 128 + coff]);
            uint2 h3 = *reinterpret_cast<const uint2*>(&g_hh[(size_t)s3 * 128 + coff]);
            float ex0 = __shfl_sync(0xffffffffu, ex_reg[t], jl + 0);
            float ex1 = __shfl_sync(0xffffffffu, ex_reg[t], jl + 1);
            float ex2 = __shfl_sync(0xffffffffu, ex_reg[t], jl + 2);
            float ex3 = __shfl_sync(0xffffffffu, ex_reg[t], jl + 3);
            float2 a0 = __half22float2(*reinterpret_cast<const __half2*>(&h0.x));
            float2 b0 = __half22float2(*reinterpret_cast<const __half2*>(&h0.y));
            float2 a1 = __half22float2(*reinterpret_cast<const __half2*>(&h1.x));
            float2 b1 = __half22float2(*reinterpret_cast<const __half2*>(&h1.y));
            float2 a2 = __half22float2(*reinterpret_cast<const __half2*>(&h2.x));
            float2 b2 = __half22float2(*reinterpret_cast<const __half2*>(&h2.y));
            float2 a3 = __half22float2(*reinterpret_cast<const __half2*>(&h3.x));
            float2 b3 = __half22float2(*reinterpret_cast<const __half2*>(&h3.y));
            acc.x += ex0 * a0.x + ex1 * a1.x + ex2 * a2.x + ex3 * a3.x;
            acc.y += ex0 * a0.y + ex1 * a1.y + ex2 * a2.y + ex3 * a3.y;
            acc.z += ex0 * b0.x + ex1 * b1.x + ex2 * b2.x + ex3 * b3.x;
            acc.w += ex0 * b0.y + ex1 * b1.y + ex2 * b2.y + ex3 * b3.y;
        }
        for (; jl < cnt; jl++) {
            int s0 = __shfl_sync(0xffffffffu, s_reg[t], jl);
            float ex0 = __shfl_sync(0xffffffffu, ex_reg[t], jl);
            uint2 h0 = *reinterpret_cast<const uint2*>(&g_hh[(size_t)s0 * 128 + coff]);
            float2 a0 = __half22float2(*reinterpret_cast<const __half2*>(&h0.x));
            float2 b0 = __half22float2(*reinterpret_cast<const __half2*>(&h0.y));
            acc.x += ex0 * a0.x;
            acc.y += ex0 * a0.y;
            acc.z += ex0 * b0.x;
            acc.w += ex0 * b0.y;
        }
    }
    if (deg > 96) {
        for (int j = rp + 96; j < re; j++) {
            int s = g_srcidx[j];
            float e = g_ss[s] + sd;
            e = e > 0.f ? e : 0.2f * e;
            float ex = __expf(e - mx);
            denom += ex;
            uint2 h0 = *reinterpret_cast<const uint2*>(&g_hh[(size_t)s * 128 + coff]);
            float2 a0 = __half22float2(*reinterpret_cast<const __half2*>(&h0.x));
            float2 b0 = __half22float2(*reinterpret_cast<const __half2*>(&h0.y));
            acc.x += ex * a0.x;
            acc.y += ex * a0.y;
            acc.z += ex * b0.x;
            acc.w += ex * b0.y;
        }
    }

    float inv = 1.f / denom;
    float4 o;
    o.x = fmaxf(fmaf(acc.x, inv, bias[coff + 0]), 0.f);
    o.y = fmaxf(fmaf(acc.y, inv, bias[coff + 1]), 0.f);
    o.z = fmaxf(fmaf(acc.z, inv, bias[coff + 2]), 0.f);
    o.w = fmaxf(fmaf(acc.w, inv, bias[coff + 3]), 0.f);
    *reinterpret_cast<float4*>(&g_feat[(size_t)warp * 128 + coff]) = o;
}

// ---------------- layer2 aggregation (C<=64) + fused log_softmax ------------
__global__ __launch_bounds__(256) void k_agg2(const float* __restrict__ bias,
                                              float* __restrict__ out, int N, int C) {
    int warp = (blockIdx.x * blockDim.x + threadIdx.x) >> 5;
    int lane = threadIdx.x & 31;
    if (warp >= N) return;
    int rp = g_rowptr[warp], re = g_rowptr[warp + 1];
    int deg = re - rp;
    float sd = g_sd[warp];

    int s_reg[3];
    float e_reg[3];
    float mx = NEG_INF;
#pragma unroll
    for (int t = 0; t < 3; t++) {
        int j = rp + t * 32 + lane;
        bool ok = j < re;
        int s = ok ? g_srcidx[j] : 0;
        s_reg[t] = s;
        float e = ok ? (g_ss[s] + sd) : NEG_INF;
        if (ok) e = e > 0.f ? e : 0.2f * e;
        e_reg[t] = e;
        mx = fmaxf(mx, e);
    }
    for (int j = rp + 96 + lane; j < re; j += 32) {
        float e = g_ss[g_srcidx[j]] + sd;
        e = e > 0.f ? e : 0.2f * e;
        mx = fmaxf(mx, e);
    }
#pragma unroll
    for (int o = 16; o; o >>= 1) mx = fmaxf(mx, __shfl_xor_sync(0xffffffffu, mx, o));

    float ex_reg[3];
    float dsum = 0.f;
#pragma unroll
    for (int t = 0; t < 3; t++) {
        float ex = (e_reg[t] > NEG_INF) ? __expf(e_reg[t] - mx) : 0.f;
        ex_reg[t] = ex;
        dsum += ex;
    }
#pragma unroll
    for (int o = 16; o; o >>= 1) dsum += __shfl_xor_sync(0xffffffffu, dsum, o);
    float denom = dsum;

    int c0 = lane, c1 = lane + 32;
    bool v0ok = c0 < C, v1ok = c1 < C;
    float a0 = 0.f, a1 = 0.f;
    int jmax = min(deg, 96);
#pragma unroll
    for (int t = 0; t < 3; t++) {
        int base = t * 32;
        if (base >= jmax) break;
        int cnt = min(32, jmax - base);
        int jl = 0;
        for (; jl + 4 <= cnt; jl += 4) {
            int s0 = __shfl_sync(0xffffffffu, s_reg[t], jl + 0);
            int s1 = __shfl_sync(0xffffffffu, s_reg[t], jl + 1);
            int s2 = __shfl_sync(0xffffffffu, s_reg[t], jl + 2);
            int s3 = __shfl_sync(0xffffffffu, s_reg[t], jl + 3);
            float h00 = v0ok ? __half2float(g_hh[(size_t)s0 * C + c0]) : 0.f;
            float h10 = v0ok ? __half2float(g_hh[(size_t)s1 * C + c0]) : 0.f;
            float h20 = v0ok ? __half2float(g_hh[(size_t)s2 * C + c0]) : 0.f;
            float h30 = v0ok ? __half2float(g_hh[(size_t)s3 * C + c0]) : 0.f;
            float h01 = v1ok ? __half2float(g_hh[(size_t)s0 * C + c1]) : 0.f;
            float h11 = v1ok ? __half2float(g_hh[(size_t)s1 * C + c1]) : 0.f;
            float h21 = v1ok ? __half2float(g_hh[(size_t)s2 * C + c1]) : 0.f;
            float h31 = v1ok ? __half2float(g_hh[(size_t)s3 * C + c1]) : 0.f;
            float ex0 = __shfl_sync(0xffffffffu, ex_reg[t], jl + 0);
            float ex1 = __shfl_sync(0xffffffffu, ex_reg[t], jl + 1);
            float ex2 = __shfl_sync(0xffffffffu, ex_reg[t], jl + 2);
            float ex3 = __shfl_sync(0xffffffffu, ex_reg[t], jl + 3);
            a0 += ex0 * h00 + ex1 * h10 + ex2 * h20 + ex3 * h30;
            a1 += ex0 * h01 + ex1 * h11 + ex2 * h21 + ex3 * h31;
        }
        for (; jl < cnt; jl++) {
            int s0 = __shfl_sync(0xffffffffu, s_reg[t], jl);
            float ex0 = __shfl_sync(0xffffffffu, ex_reg[t], jl);
            float h00 = v0ok ? __half2float(g_hh[(size_t)s0 * C + c0]) : 0.f;
            float h01 = v1ok ? __half2float(g_hh[(size_t)s0 * C + c1]) : 0.f;
            a0 += ex0 * h00;
            a1 += ex0 * h01;
        }
    }
    if (deg > 96) {
        for (int j = rp + 96; j < re; j++) {
            int s = g_srcidx[j];
            float e = g_ss[s] + sd;
            e = e > 0.f ? e : 0.2f * e;
            float ex = __expf(e - mx);
            denom += ex;
            float h00 = v0ok ? __half2float(g_hh[(size_t)s * C + c0]) : 0.f;
            float h01 = v1ok ? __half2float(g_hh[(size_t)s * C + c1]) : 0.f;
            a0 += ex * h00;
            a1 += ex * h01;
        }
    }

    float inv = 1.f / denom;
    float v0 = v0ok ? fmaf(a0, inv, bias[c0]) : NEG_INF;
    float v1 = v1ok ? fmaf(a1, inv, bias[c1]) : NEG_INF;
    float m2 = fmaxf(v0, v1);
#pragma unroll
    for (int o = 16; o; o >>= 1) m2 = fmaxf(m2, __shfl_xor_sync(0xffffffffu, m2, o));
    float se = (v0ok ? __expf(v0 - m2) : 0.f) + (v1ok ? __expf(v1 - m2) : 0.f);
#pragma unroll
    for (int o = 16; o; o >>= 1) se += __shfl_xor_sync(0xffffffffu, se, o);
    float lse = m2 + logf(se);
    if (v0ok) out[(size_t)warp * C + c0] = v0 - lse;
    if (v1ok) out[(size_t)warp * C + c1] = v1 - lse;
}

// ---------------- launcher --------------------------------------------------
static inline int cdiv(int a, int b) { return (a + b - 1) / b; }

extern "C" void kernel_launch(void* const* d_in, const int* in_sizes, int n_in,
                              void* d_out, int out_size) {
    const float* x   = (const float*)d_in[0];
    const int* ei32  = (const int*)d_in[1];
    const float* W1  = (const float*)d_in[2];
    const float* as1 = (const float*)d_in[3];
    const float* ad1 = (const float*)d_in[4];
    const float* b1  = (const float*)d_in[5];
    const float* W2  = (const float*)d_in[6];
    const float* as2 = (const float*)d_in[7];
    const float* ad2 = (const float*)d_in[8];
    const float* b2  = (const float*)d_in[9];

    int H = in_sizes[3];
    int C = in_sizes[7];
    int F = in_sizes[2] / H;
    int N = in_sizes[0] / F;
    int E = in_sizes[1] / 2;

    static cudaStream_t side = nullptr;
    static cudaEvent_t evFork = nullptr, evJoin = nullptr;
    if (side == nullptr) {
        cudaStreamCreateWithFlags(&side, cudaStreamNonBlocking);
        cudaEventCreateWithFlags(&evFork, cudaEventDisableTiming);
        cudaEventCreateWithFlags(&evJoin, cudaEventDisableTiming);
    }

    cudaEventRecord(evFork, 0);
    cudaStreamWaitEvent(side, evFork, 0);

    int nb = cdiv(N, SCAN_CHUNK);
    k_initdeg<<<cdiv(N, 256), 256, 0, side>>>(ei32, N);
    k_count<<<cdiv(E, 256), 256, 0, side>>>(ei32, E);
    k_scan_blocksum<<<nb, 256, 0, side>>>(N);
    k_scan_partials<<<1, 32, 0, side>>>(nb, N);
    k_scan_blockscan<<<nb, 256, 0, side>>>(N);
    k_fill<<<cdiv(E + N, 256), 256, 0, side>>>(ei32, E, N);

    dim3 g1(cdiv(H, 128), cdiv(N, 128));
    const float* s1 = (g1.x == 1) ? as1 : nullptr;
    k_gemm_bf16<<<g1, 256>>>(N, H, F, x, W1, 0, s1, ad1);

    cudaEventRecord(evJoin, side);
    cudaStreamWaitEvent(0, evJoin, 0);

    k_agg1<<<cdiv(N, 8), 256>>>(b1, N);

    dim3 g2(cdiv(C, 128), cdiv(N, 128));
    const float* s2 = (g2.x == 1) ? as2 : nullptr;
    k_gemm_bf16<<<g2, 256>>>(N, C, H, nullptr, W2, 1, s2, ad2);
    k_agg2<<<cdiv(N, 8), 256>>>(b2, (float*)d_out, N, C);
}